// round 1
// baseline (speedup 1.0000x reference)
#include <cuda_runtime.h>
#include <math.h>

#define Bn   2
#define Tn   1024
#define Cn   1024
#define Hn   16
#define HSn  64
#define ROTn 32
#define TTn  1024
#define FFNn 4096
#define EPSn 1e-6f

// ---------------- scratch (device globals; no allocations allowed) ----------
__device__ float g_xs [Bn*Tn*Cn];          // time-shifted LN1 output
__device__ float g_q  [Bn*Tn*Cn];          // (B,H,T,HS)
__device__ float g_k  [Bn*Tn*Cn];
__device__ float g_v  [Bn*Tn*Cn];
__device__ float g_att [Bn*Hn*Tn*Tn];      // 128 MB
__device__ float g_att2[Bn*Hn*Tn*Tn];      // 128 MB
__device__ float g_y  [Bn*Tn*Cn];          // attn out, (B,T,C)
__device__ float g_x1 [Bn*Tn*Cn];          // residual 1
__device__ float g_xm [Bn*Tn*Cn];          // LN2 output
__device__ float g_kk [Bn*Tn*FFNn];        // gelu(kk)
__device__ float g_gv [Bn*Tn*FFNn];        // gelu(kk)*vv

// ---------------- block reductions ----------------
__device__ __forceinline__ float blockReduceSum(float v, float* sh) {
    int tid = threadIdx.x;
    sh[tid] = v; __syncthreads();
    for (int s = 128; s > 0; s >>= 1) {
        if (tid < s) sh[tid] += sh[tid + s];
        __syncthreads();
    }
    float r = sh[0]; __syncthreads();
    return r;
}
__device__ __forceinline__ float blockReduceMax(float v, float* sh) {
    int tid = threadIdx.x;
    sh[tid] = v; __syncthreads();
    for (int s = 128; s > 0; s >>= 1) {
        if (tid < s) sh[tid] = fmaxf(sh[tid], sh[tid + s]);
        __syncthreads();
    }
    float r = sh[0]; __syncthreads();
    return r;
}

// ---------------- LN1 + time_shift_half ----------------
// block per (b,t); writes first half of LN row to t+1, second half to t.
__global__ void ln1_shift_kernel(const float* __restrict__ x,
                                 const float* __restrict__ g,
                                 const float* __restrict__ b) {
    __shared__ float sh[256];
    int bt = blockIdx.x;
    int bb = bt / Tn, t = bt % Tn;
    const float* row = x + (size_t)bt * Cn;
    float s = 0.f, s2 = 0.f;
    for (int c = threadIdx.x; c < Cn; c += 256) {
        float v = row[c]; s += v; s2 += v * v;
    }
    s  = blockReduceSum(s,  sh);
    s2 = blockReduceSum(s2, sh);
    float m    = s / Cn;
    float var  = s2 / Cn - m * m;
    float rstd = rsqrtf(var + EPSn);
    for (int c = threadIdx.x; c < Cn; c += 256) {
        float yv = (row[c] - m) * rstd * g[c] + b[c];
        if (c < Cn / 2) {
            if (t + 1 < Tn) g_xs[((size_t)bb * Tn + t + 1) * Cn + c] = yv;
        } else {
            g_xs[(size_t)bt * Cn + c] = yv;
        }
    }
    if (t == 0) {
        for (int c = threadIdx.x; c < Cn / 2; c += 256)
            g_xs[(size_t)bb * Tn * Cn + c] = 0.f;
    }
}

// ---------------- plain LayerNorm ----------------
__global__ void ln_kernel(const float* __restrict__ in,
                          const float* __restrict__ g,
                          const float* __restrict__ b,
                          float* __restrict__ out) {
    __shared__ float sh[256];
    int bt = blockIdx.x;
    const float* row = in + (size_t)bt * Cn;
    float s = 0.f, s2 = 0.f;
    for (int c = threadIdx.x; c < Cn; c += 256) {
        float v = row[c]; s += v; s2 += v * v;
    }
    s  = blockReduceSum(s,  sh);
    s2 = blockReduceSum(s2, sh);
    float m    = s / Cn;
    float rstd = rsqrtf(s2 / Cn - m * m + EPSn);
    for (int c = threadIdx.x; c < Cn; c += 256)
        out[(size_t)bt * Cn + c] = (row[c] - m) * rstd * g[c] + b[c];
}

// ---------------- generic 64x64x16 SGEMM (A,B row-major, NN) ----------------
// modes: 0 plain, 1 qkv-scatter, 2 outproj(gamma,res), 3 gelu, 4 mul aux, 5 add res
#define EPI_PLAIN 0
#define EPI_QKV   1
#define EPI_OUT   2
#define EPI_GELU  3
#define EPI_MUL   4
#define EPI_ADD   5

__global__ __launch_bounds__(256)
void gemm64(const float* __restrict__ A, const float* __restrict__ Bm,
            const float* __restrict__ bias, float* __restrict__ C,
            int M, int N, int K, int mode,
            const float* __restrict__ aux1, const float* __restrict__ aux2) {
    __shared__ float As[16][68];   // transposed A tile, padded (16B-aligned rows)
    __shared__ float Bs[16][64];
    int tid = threadIdx.x;
    int row0 = blockIdx.y * 64, col0 = blockIdx.x * 64;
    int tx = tid % 16, ty = tid / 16;
    int ar = tid / 4,  akq = (tid % 4) * 4;
    int bkk = tid / 16, bc = (tid % 16) * 4;
    float acc[4][4] = {};

    for (int k0 = 0; k0 < K; k0 += 16) {
        float4 av = *(const float4*)(A + (size_t)(row0 + ar) * K + k0 + akq);
        As[akq + 0][ar] = av.x; As[akq + 1][ar] = av.y;
        As[akq + 2][ar] = av.z; As[akq + 3][ar] = av.w;
        float4 bv = *(const float4*)(Bm + (size_t)(k0 + bkk) * N + col0 + bc);
        *(float4*)&Bs[bkk][bc] = bv;
        __syncthreads();
#pragma unroll
        for (int kk = 0; kk < 16; kk++) {
            float4 ra = *(const float4*)&As[kk][ty * 4];
            float4 rb = *(const float4*)&Bs[kk][tx * 4];
            float a4[4] = {ra.x, ra.y, ra.z, ra.w};
            float b4[4] = {rb.x, rb.y, rb.z, rb.w};
#pragma unroll
            for (int i = 0; i < 4; i++)
#pragma unroll
                for (int j = 0; j < 4; j++)
                    acc[i][j] += a4[i] * b4[j];
        }
        __syncthreads();
    }

#pragma unroll
    for (int i = 0; i < 4; i++) {
        int r = row0 + ty * 4 + i;
#pragma unroll
        for (int j = 0; j < 4; j++) {
            int c = col0 + tx * 4 + j;
            float v = acc[i][j] + (bias ? bias[c] : 0.f);
            size_t oidx = (size_t)r * N + c;
            switch (mode) {
            case EPI_PLAIN:
                C[oidx] = v; break;
            case EPI_QKV: {
                int bI = r / Tn, t = r % Tn, h = c / HSn, d = c % HSn;
                C[(((size_t)bI * Hn + h) * Tn + t) * HSn + d] = v;
            } break;
            case EPI_OUT: {
                int t = r % Tn;
                C[oidx] = v * aux1[t] + aux2[oidx];
            } break;
            case EPI_GELU:
                C[oidx] = 0.5f * v * (1.f + erff(v * 0.70710678118654752f)); break;
            case EPI_MUL:
                C[oidx] = v * aux1[oidx]; break;
            case EPI_ADD:
                C[oidx] = v + aux1[oidx]; break;
            }
        }
    }
}

// ---------------- rotary on q,k (first 32 dims of each head) ----------------
__global__ void rotary_kernel() {
    int idx = blockIdx.x * blockDim.x + threadIdx.x;
    if (idx >= Bn * Hn * Tn * 16) return;
    int i = idx & 15;
    int bht = idx >> 4;
    int t = bht % Tn;
    float inv = powf((float)TTn, -(float)i / 16.0f);
    float ang = (float)t * inv;
    float cv = cosf(ang), sv = sinf(ang);
    float* qp = g_q + (size_t)bht * HSn;
    float* kp = g_k + (size_t)bht * HSn;
    float a = qp[i], b2 = qp[i + 16];
    qp[i]      = a * cv - b2 * sv;
    qp[i + 16] = b2 * cv + a * sv;
    a = kp[i]; b2 = kp[i + 16];
    kp[i]      = a * cv - b2 * sv;
    kp[i + 16] = b2 * cv + a * sv;
}

// ---------------- attention scores: att = q @ k^T * scale (NT, causal skip) --
__global__ __launch_bounds__(256)
void scores_kernel() {
    int z = blockIdx.z;                         // b*H + h
    int row0 = blockIdx.y * 64;                 // t
    int col0 = blockIdx.x * 64;                 // u
    if (col0 > row0 + 63) return;               // strictly above diagonal
    const float* q = g_q + (size_t)z * Tn * HSn;
    const float* k = g_k + (size_t)z * Tn * HSn;
    __shared__ float As[16][68];
    __shared__ float Bs[16][68];
    int tid = threadIdx.x;
    int tx = tid % 16, ty = tid / 16;
    int r = tid / 4, kq = (tid % 4) * 4;
    float acc[4][4] = {};
    for (int k0 = 0; k0 < HSn; k0 += 16) {
        float4 av = *(const float4*)(q + (size_t)(row0 + r) * HSn + k0 + kq);
        As[kq + 0][r] = av.x; As[kq + 1][r] = av.y;
        As[kq + 2][r] = av.z; As[kq + 3][r] = av.w;
        float4 bv = *(const float4*)(k + (size_t)(col0 + r) * HSn + k0 + kq);
        Bs[kq + 0][r] = bv.x; Bs[kq + 1][r] = bv.y;
        Bs[kq + 2][r] = bv.z; Bs[kq + 3][r] = bv.w;
        __syncthreads();
#pragma unroll
        for (int kk = 0; kk < 16; kk++) {
            float4 ra = *(const float4*)&As[kk][ty * 4];
            float4 rb = *(const float4*)&Bs[kk][tx * 4];
            float a4[4] = {ra.x, ra.y, ra.z, ra.w};
            float b4[4] = {rb.x, rb.y, rb.z, rb.w};
#pragma unroll
            for (int i = 0; i < 4; i++)
#pragma unroll
                for (int j = 0; j < 4; j++)
                    acc[i][j] += a4[i] * b4[j];
        }
        __syncthreads();
    }
    float* out = g_att + (size_t)z * Tn * Tn;
#pragma unroll
    for (int i = 0; i < 4; i++)
#pragma unroll
        for (int j = 0; j < 4; j++)
            out[(size_t)(row0 + ty * 4 + i) * Tn + col0 + tx * 4 + j] =
                acc[i][j] * 0.125f;
}

// ---------------- softmax (causal) * w, zero for u>t ----------------
__global__ void softmax_w_kernel(const float* __restrict__ time_w,
                                 const float* __restrict__ alpha,
                                 const float* __restrict__ beta) {
    __shared__ float sh[256];
    int t = blockIdx.x;
    int z = blockIdx.y;          // b*H + h
    int h = z % Hn;
    float* arow = g_att + ((size_t)z * Tn + t) * Tn;
    int len = t + 1;
    float mx = -1e30f;
    for (int u = threadIdx.x; u < len; u += 256) mx = fmaxf(mx, arow[u]);
    mx = blockReduceMax(mx, sh);
    float sum = 0.f;
    for (int u = threadIdx.x; u < len; u += 256) sum += expf(arow[u] - mx);
    sum = blockReduceSum(sum, sh);
    float inv = 1.f / sum;
    float bt = beta[h * Tn + t];
    for (int u = threadIdx.x; u < Tn; u += 256) {
        if (u < len) {
            float w = time_w[h * TTn + (TTn - 1 - t + u)] * alpha[h * Tn + u] * bt;
            arow[u] = expf(arow[u] - mx) * inv * w;
        } else {
            arow[u] = 0.f;
        }
    }
}

// ---------------- head mixing: att2[b,i] = sum_j Wmix[i,j] * att[b,j] --------
__global__ void mix_kernel(const float* __restrict__ Wmix) {
    __shared__ float wm[256];
    if (threadIdx.x < 256) wm[threadIdx.x] = Wmix[threadIdx.x];
    __syncthreads();
    int idx = blockIdx.x * 256 + threadIdx.x;
    if (idx >= Bn * Tn * Tn) return;
    int b = idx / (Tn * Tn);
    int rr = idx % (Tn * Tn);
    int t = rr / Tn, u = rr % Tn;
    size_t base = (size_t)b * Hn * Tn * Tn + rr;
    const size_t stride = (size_t)Tn * Tn;
    if (u > t) {
#pragma unroll
        for (int i = 0; i < Hn; i++) g_att2[base + i * stride] = 0.f;
        return;
    }
    float vals[Hn];
#pragma unroll
    for (int j = 0; j < Hn; j++) vals[j] = g_att[base + j * stride];
#pragma unroll
    for (int i = 0; i < Hn; i++) {
        float s = 0.f;
#pragma unroll
        for (int j = 0; j < Hn; j++) s += wm[i * Hn + j] * vals[j];
        g_att2[base + i * stride] = s;
    }
}

// ---------------- y = att2 @ v (NN, K clipped by causality) -----------------
__global__ __launch_bounds__(256)
void av_kernel() {
    int z = blockIdx.z;                 // b*H + h
    int row0 = blockIdx.y * 64;         // t
    const float* Am = g_att2 + (size_t)z * Tn * Tn;
    const float* Vm = g_v    + (size_t)z * Tn * HSn;
    __shared__ float As[16][68];
    __shared__ float Bs[16][64];
    int tid = threadIdx.x;
    int tx = tid % 16, ty = tid / 16;
    int ar = tid / 4, akq = (tid % 4) * 4;
    int bkk = tid / 16, bc = (tid % 16) * 4;
    float acc[4][4] = {};
    int klim = row0 + 64;               // u <= t within this row tile
    for (int k0 = 0; k0 < klim; k0 += 16) {
        float4 av = *(const float4*)(Am + (size_t)(row0 + ar) * Tn + k0 + akq);
        As[akq + 0][ar] = av.x; As[akq + 1][ar] = av.y;
        As[akq + 2][ar] = av.z; As[akq + 3][ar] = av.w;
        float4 bv = *(const float4*)(Vm + (size_t)(k0 + bkk) * HSn + bc);
        *(float4*)&Bs[bkk][bc] = bv;
        __syncthreads();
#pragma unroll
        for (int kk = 0; kk < 16; kk++) {
            float4 ra = *(const float4*)&As[kk][ty * 4];
            float4 rb = *(const float4*)&Bs[kk][tx * 4];
            float a4[4] = {ra.x, ra.y, ra.z, ra.w};
            float b4[4] = {rb.x, rb.y, rb.z, rb.w};
#pragma unroll
            for (int i = 0; i < 4; i++)
#pragma unroll
                for (int j = 0; j < 4; j++)
                    acc[i][j] += a4[i] * b4[j];
        }
        __syncthreads();
    }
    int b = z / Hn, h = z % Hn;
#pragma unroll
    for (int i = 0; i < 4; i++) {
        int t = row0 + ty * 4 + i;
#pragma unroll
        for (int j = 0; j < 4; j++) {
            int d = tx * 4 + j;
            g_y[((size_t)b * Tn + t) * Cn + h * HSn + d] = acc[i][j];
        }
    }
}

// ---------------- launch ----------------
extern "C" void kernel_launch(void* const* d_in, const int* in_sizes, int n_in,
                              void* d_out, int out_size) {
    const float* x         = (const float*)d_in[0];
    const float* ln1_g     = (const float*)d_in[1];
    const float* ln1_b     = (const float*)d_in[2];
    const float* Wq        = (const float*)d_in[3];
    const float* bq        = (const float*)d_in[4];
    const float* Wk        = (const float*)d_in[5];
    const float* bk        = (const float*)d_in[6];
    const float* Wv        = (const float*)d_in[7];
    const float* bv        = (const float*)d_in[8];
    const float* Wo        = (const float*)d_in[9];
    const float* bo        = (const float*)d_in[10];
    const float* time_w    = (const float*)d_in[11];
    const float* time_alpha= (const float*)d_in[12];
    const float* time_beta = (const float*)d_in[13];
    const float* time_gamma= (const float*)d_in[14];
    const float* Wmix      = (const float*)d_in[15];
    const float* ln2_g     = (const float*)d_in[16];
    const float* ln2_b     = (const float*)d_in[17];
    const float* Wgk       = (const float*)d_in[18];
    const float* bgk       = (const float*)d_in[19];
    const float* Wgv       = (const float*)d_in[20];
    const float* bgv       = (const float*)d_in[21];
    const float* Wgw       = (const float*)d_in[22];
    const float* bgw       = (const float*)d_in[23];

    float *xs, *q, *k, *v, *x1, *xm, *kkb, *gvb, *yb;
    cudaGetSymbolAddress((void**)&xs,  g_xs);
    cudaGetSymbolAddress((void**)&q,   g_q);
    cudaGetSymbolAddress((void**)&k,   g_k);
    cudaGetSymbolAddress((void**)&v,   g_v);
    cudaGetSymbolAddress((void**)&yb,  g_y);
    cudaGetSymbolAddress((void**)&x1,  g_x1);
    cudaGetSymbolAddress((void**)&xm,  g_xm);
    cudaGetSymbolAddress((void**)&kkb, g_kk);
    cudaGetSymbolAddress((void**)&gvb, g_gv);

    const int M = Bn * Tn;   // 2048

    // 1) LN1 + time shift
    ln1_shift_kernel<<<Bn * Tn, 256>>>(x, ln1_g, ln1_b);

    // 2) QKV projections (scatter to (B,H,T,HS))
    dim3 gCC(Cn / 64, M / 64);
    gemm64<<<gCC, 256>>>(xs, Wq, bq, q, M, Cn, Cn, EPI_QKV, nullptr, nullptr);
    gemm64<<<gCC, 256>>>(xs, Wk, bk, k, M, Cn, Cn, EPI_QKV, nullptr, nullptr);
    gemm64<<<gCC, 256>>>(xs, Wv, bv, v, M, Cn, Cn, EPI_QKV, nullptr, nullptr);

    // 3) rotary on q,k
    rotary_kernel<<<(Bn * Hn * Tn * 16) / 256, 256>>>();

    // 4) attention scores (causal tiles only)
    scores_kernel<<<dim3(Tn / 64, Tn / 64, Bn * Hn), 256>>>();

    // 5) softmax * w
    softmax_w_kernel<<<dim3(Tn, Bn * Hn), 256>>>(time_w, time_alpha, time_beta);

    // 6) head mix
    mix_kernel<<<(Bn * Tn * Tn) / 256, 256>>>(Wmix);

    // 7) y = att2 @ v
    av_kernel<<<dim3(1, Tn / 64, Bn * Hn), 256>>>();

    // 8) out projection: x1 = x + (y@Wo + bo)*gamma
    gemm64<<<gCC, 256>>>(yb, Wo, bo, x1, M, Cn, Cn, EPI_OUT, time_gamma, x);

    // 9) LN2
    ln_kernel<<<Bn * Tn, 256>>>(x1, ln2_g, ln2_b, xm);

    // 10-12) FFN
    dim3 gCF(FFNn / 64, M / 64);
    gemm64<<<gCF, 256>>>(xm, Wgk, bgk, kkb, M, FFNn, Cn, EPI_GELU, nullptr, nullptr);
    gemm64<<<gCF, 256>>>(xm, Wgv, bgv, gvb, M, FFNn, Cn, EPI_MUL, kkb, nullptr);
    gemm64<<<gCC, 256>>>(gvb, Wgw, bgw, (float*)d_out, M, Cn, FFNn, EPI_ADD, x1, nullptr);
}

// round 3
// speedup vs baseline: 3.6161x; 3.6161x over previous
#include <cuda_runtime.h>
#include <cstdint>
#include <math.h>

#define Bn   2
#define Tn   1024
#define Cn   1024
#define Hn   16
#define HSn  64
#define TTn  1024
#define FFNn 4096
#define EPSn 1e-6f

// ---------------- scratch (device globals; no allocations allowed) ----------
__device__ float g_xs [Bn*Tn*Cn];
__device__ float g_q  [Bn*Tn*Cn];
__device__ float g_k  [Bn*Tn*Cn];
__device__ float g_v  [Bn*Tn*Cn];
__device__ float g_att [Bn*Hn*Tn*Tn];
__device__ float g_att2[Bn*Hn*Tn*Tn];
__device__ float g_y  [Bn*Tn*Cn];
__device__ float g_x1 [Bn*Tn*Cn];
__device__ float g_xm [Bn*Tn*Cn];
__device__ float g_kk [Bn*Tn*FFNn];
__device__ float g_gv [Bn*Tn*FFNn];

// ---------------- helpers ----------------
__device__ __forceinline__ uint32_t f2tf32(float v) {
    uint32_t t;
    asm("cvt.rna.tf32.f32 %0, %1;" : "=r"(t) : "f"(v));
    return t;
}
__device__ __forceinline__ void mma_tf32(float* d, const uint32_t* a, const uint32_t* b) {
    asm volatile(
        "mma.sync.aligned.m16n8k8.row.col.f32.tf32.tf32.f32 "
        "{%0,%1,%2,%3}, {%4,%5,%6,%7}, {%8,%9}, {%0,%1,%2,%3};"
        : "+f"(d[0]), "+f"(d[1]), "+f"(d[2]), "+f"(d[3])
        : "r"(a[0]), "r"(a[1]), "r"(a[2]), "r"(a[3]), "r"(b[0]), "r"(b[1]));
}

// ---------------- block reductions ----------------
__device__ __forceinline__ float blockReduceSum(float v, float* sh) {
    int tid = threadIdx.x;
    sh[tid] = v; __syncthreads();
    for (int s = 128; s > 0; s >>= 1) {
        if (tid < s) sh[tid] += sh[tid + s];
        __syncthreads();
    }
    float r = sh[0]; __syncthreads();
    return r;
}
__device__ __forceinline__ float blockReduceMax(float v, float* sh) {
    int tid = threadIdx.x;
    sh[tid] = v; __syncthreads();
    for (int s = 128; s > 0; s >>= 1) {
        if (tid < s) sh[tid] = fmaxf(sh[tid], sh[tid + s]);
        __syncthreads();
    }
    float r = sh[0]; __syncthreads();
    return r;
}

// ---------------- LN1 + time_shift_half ----------------
__global__ void ln1_shift_kernel(const float* __restrict__ x,
                                 const float* __restrict__ g,
                                 const float* __restrict__ b) {
    __shared__ float sh[256];
    int bt = blockIdx.x;
    int bb = bt / Tn, t = bt % Tn;
    const float* row = x + (size_t)bt * Cn;
    float s = 0.f, s2 = 0.f;
    for (int c = threadIdx.x; c < Cn; c += 256) {
        float v = row[c]; s += v; s2 += v * v;
    }
    s  = blockReduceSum(s,  sh);
    s2 = blockReduceSum(s2, sh);
    float m    = s / Cn;
    float rstd = rsqrtf(s2 / Cn - m * m + EPSn);
    for (int c = threadIdx.x; c < Cn; c += 256) {
        float yv = (row[c] - m) * rstd * g[c] + b[c];
        if (c < Cn / 2) {
            if (t + 1 < Tn) g_xs[((size_t)bb * Tn + t + 1) * Cn + c] = yv;
        } else {
            g_xs[(size_t)bt * Cn + c] = yv;
        }
    }
    if (t == 0) {
        for (int c = threadIdx.x; c < Cn / 2; c += 256)
            g_xs[(size_t)bb * Tn * Cn + c] = 0.f;
    }
}

// ---------------- plain LayerNorm ----------------
__global__ void ln_kernel(const float* __restrict__ in,
                          const float* __restrict__ g,
                          const float* __restrict__ b,
                          float* __restrict__ out) {
    __shared__ float sh[256];
    int bt = blockIdx.x;
    const float* row = in + (size_t)bt * Cn;
    float s = 0.f, s2 = 0.f;
    for (int c = threadIdx.x; c < Cn; c += 256) {
        float v = row[c]; s += v; s2 += v * v;
    }
    s  = blockReduceSum(s,  sh);
    s2 = blockReduceSum(s2, sh);
    float m    = s / Cn;
    float rstd = rsqrtf(s2 / Cn - m * m + EPSn);
    for (int c = threadIdx.x; c < Cn; c += 256)
        out[(size_t)bt * Cn + c] = (row[c] - m) * rstd * g[c] + b[c];
}

// ---------------- tf32 mma.sync GEMM: C[M,N] = A[M,K] @ B[K,N] --------------
// A row-major [M][K]; B row-major [K][N] (native weight layout).
#define EPI_QKV   1
#define EPI_OUT   2
#define EPI_GELU  3
#define EPI_MUL   4
#define EPI_ADD   5

#define ASTR 36    // smem A row stride (floats), [128][36]
#define BSTR 136   // smem B row stride (floats), [32][136]

__global__ __launch_bounds__(256)
void gemm_mma(const float* __restrict__ A, const float* __restrict__ Bm,
              const float* __restrict__ bias, float* __restrict__ C,
              int M, int N, int K, int mode,
              const float* __restrict__ aux1, const float* __restrict__ aux2) {
    __shared__ uint32_t sa[128 * ASTR];
    __shared__ uint32_t sbm[32 * BSTR];

    int tid = threadIdx.x;
    int lane = tid & 31;
    int wid  = tid >> 5;
    int wm = wid >> 2;            // 0..1  (m: 64 rows each)
    int wn = wid & 3;             // 0..3  (n: 32 cols each)
    int row0 = blockIdx.y * 128, col0 = blockIdx.x * 128;

    int lg = lane >> 2;           // lane/4: 0..7
    int lq = lane & 3;            // lane%4: 0..3

    float acc[4][4][4] = {};

    // global-load offsets
    int ar = tid >> 3;            // 0..31 (row step 32 per iter)
    int ac = (tid & 7) * 4;       // 0..28
    int br = tid >> 6;            // 0..3  (row step 4 per iter? no: see below)
    int bc = (tid & 63) * 2;      // 0..126, 2 floats each

    float4 pa[4];
    float2 pb[4];

    const int nchunks = K >> 5;

    // prefetch chunk 0
    {
        const float* Ab = A + (size_t)row0 * K;
#pragma unroll
        for (int it = 0; it < 4; it++)
            pa[it] = *(const float4*)(Ab + (size_t)(it * 32 + ar) * K + ac);
        const float* Bb = Bm + col0;
#pragma unroll
        for (int it = 0; it < 4; it++)
            pb[it] = *(const float2*)(Bb + (size_t)(it * 8 + (tid >> 6) + ((it & 0) )) * N + bc);
        // note: B rows covered: it*8 + tid/64 -> only 4 of 8 rows per it... fixed below
    }
    // Correct B prefetch: 32 rows x 128 cols = 4096 floats / 256 thr = 16 floats
    // = 8 float2 per thread. Redo with 8 iterations of 4 rows.
    float2 pb8[8];
    {
        const float* Bb = Bm + col0;
#pragma unroll
        for (int it = 0; it < 8; it++)
            pb8[it] = *(const float2*)(Bb + (size_t)(it * 4 + br) * N + bc);
    }

    for (int ci = 0; ci < nchunks; ci++) {
        __syncthreads();
        // store current prefetched chunk to smem (with tf32 rounding)
#pragma unroll
        for (int it = 0; it < 4; it++) {
            int r = it * 32 + ar;
            uint32_t* p = &sa[r * ASTR + ac];
            p[0] = f2tf32(pa[it].x); p[1] = f2tf32(pa[it].y);
            p[2] = f2tf32(pa[it].z); p[3] = f2tf32(pa[it].w);
        }
#pragma unroll
        for (int it = 0; it < 8; it++) {
            int r = it * 4 + br;
            uint32_t* p = &sbm[r * BSTR + bc];
            p[0] = f2tf32(pb8[it].x); p[1] = f2tf32(pb8[it].y);
        }
        __syncthreads();

        // prefetch next chunk
        if (ci + 1 < nchunks) {
            int k0 = (ci + 1) << 5;
            const float* Ab = A + (size_t)row0 * K + k0;
#pragma unroll
            for (int it = 0; it < 4; it++)
                pa[it] = *(const float4*)(Ab + (size_t)(it * 32 + ar) * K + ac);
            const float* Bb = Bm + (size_t)k0 * N + col0;
#pragma unroll
            for (int it = 0; it < 8; it++)
                pb8[it] = *(const float2*)(Bb + (size_t)(it * 4 + br) * N + bc);
        }

        // compute: 4 k-steps of 8
#pragma unroll
        for (int ks = 0; ks < 4; ks++) {
            int kb = ks * 8;
            uint32_t af[4][4], bf[4][2];
#pragma unroll
            for (int mi = 0; mi < 4; mi++) {
                int mr = wm * 64 + mi * 16 + lg;
                af[mi][0] = sa[mr * ASTR + kb + lq];
                af[mi][1] = sa[(mr + 8) * ASTR + kb + lq];
                af[mi][2] = sa[mr * ASTR + kb + 4 + lq];
                af[mi][3] = sa[(mr + 8) * ASTR + kb + 4 + lq];
            }
#pragma unroll
            for (int ni = 0; ni < 4; ni++) {
                int nc = wn * 32 + ni * 8 + lg;
                bf[ni][0] = sbm[(kb + lq) * BSTR + nc];
                bf[ni][1] = sbm[(kb + 4 + lq) * BSTR + nc];
            }
#pragma unroll
            for (int mi = 0; mi < 4; mi++)
#pragma unroll
                for (int ni = 0; ni < 4; ni++)
                    mma_tf32(acc[mi][ni], af[mi], bf[ni]);
        }
    }

    // epilogue
#pragma unroll
    for (int mi = 0; mi < 4; mi++) {
#pragma unroll
        for (int ni = 0; ni < 4; ni++) {
#pragma unroll
            for (int half = 0; half < 2; half++) {
                int r = row0 + wm * 64 + mi * 16 + lg + half * 8;
                int c = col0 + wn * 32 + ni * 8 + lq * 2;
                float v0 = acc[mi][ni][half * 2 + 0] + bias[c];
                float v1 = acc[mi][ni][half * 2 + 1] + bias[c + 1];
                size_t oi = (size_t)r * N + c;
                switch (mode) {
                case EPI_QKV: {
                    int bI = r / Tn, t = r % Tn, h = c / HSn, d = c % HSn;
                    size_t qi = (((size_t)bI * Hn + h) * Tn + t) * HSn + d;
                    C[qi] = v0; C[qi + 1] = v1;
                } break;
                case EPI_OUT: {
                    int t = r % Tn;
                    C[oi]     = v0 * aux1[t] + aux2[oi];
                    C[oi + 1] = v1 * aux1[t] + aux2[oi + 1];
                } break;
                case EPI_GELU:
                    C[oi]     = 0.5f * v0 * (1.f + erff(v0 * 0.70710678118654752f));
                    C[oi + 1] = 0.5f * v1 * (1.f + erff(v1 * 0.70710678118654752f));
                    break;
                case EPI_MUL:
                    C[oi]     = v0 * aux1[oi];
                    C[oi + 1] = v1 * aux1[oi + 1];
                    break;
                case EPI_ADD:
                    C[oi]     = v0 + aux1[oi];
                    C[oi + 1] = v1 + aux1[oi + 1];
                    break;
                default:
                    C[oi] = v0; C[oi + 1] = v1;
                }
            }
        }
    }
}

// ---------------- rotary on q,k ----------------
__global__ void rotary_kernel() {
    int idx = blockIdx.x * blockDim.x + threadIdx.x;
    if (idx >= Bn * Hn * Tn * 16) return;
    int i = idx & 15;
    int bht = idx >> 4;
    int t = bht % Tn;
    float inv = powf((float)TTn, -(float)i / 16.0f);
    float ang = (float)t * inv;
    float cv = cosf(ang), sv = sinf(ang);
    float* qp = g_q + (size_t)bht * HSn;
    float* kp = g_k + (size_t)bht * HSn;
    float a = qp[i], b2 = qp[i + 16];
    qp[i]      = a * cv - b2 * sv;
    qp[i + 16] = b2 * cv + a * sv;
    a = kp[i]; b2 = kp[i + 16];
    kp[i]      = a * cv - b2 * sv;
    kp[i + 16] = b2 * cv + a * sv;
}

// ---------------- attention scores (fp32, causal skip) ----------------
__global__ __launch_bounds__(256)
void scores_kernel() {
    int z = blockIdx.z;
    int row0 = blockIdx.y * 64;
    int col0 = blockIdx.x * 64;
    if (col0 > row0 + 63) return;
    const float* q = g_q + (size_t)z * Tn * HSn;
    const float* k = g_k + (size_t)z * Tn * HSn;
    __shared__ float As[16][68];
    __shared__ float Bs[16][68];
    int tid = threadIdx.x;
    int tx = tid % 16, ty = tid / 16;
    int r = tid / 4, kq = (tid % 4) * 4;
    float acc[4][4] = {};
    for (int k0 = 0; k0 < HSn; k0 += 16) {
        float4 av = *(const float4*)(q + (size_t)(row0 + r) * HSn + k0 + kq);
        As[kq + 0][r] = av.x; As[kq + 1][r] = av.y;
        As[kq + 2][r] = av.z; As[kq + 3][r] = av.w;
        float4 bv = *(const float4*)(k + (size_t)(col0 + r) * HSn + k0 + kq);
        Bs[kq + 0][r] = bv.x; Bs[kq + 1][r] = bv.y;
        Bs[kq + 2][r] = bv.z; Bs[kq + 3][r] = bv.w;
        __syncthreads();
#pragma unroll
        for (int kk = 0; kk < 16; kk++) {
            float4 ra = *(const float4*)&As[kk][ty * 4];
            float4 rb = *(const float4*)&Bs[kk][tx * 4];
            float a4[4] = {ra.x, ra.y, ra.z, ra.w};
            float b4[4] = {rb.x, rb.y, rb.z, rb.w};
#pragma unroll
            for (int i = 0; i < 4; i++)
#pragma unroll
                for (int j = 0; j < 4; j++)
                    acc[i][j] += a4[i] * b4[j];
        }
        __syncthreads();
    }
    float* out = g_att + (size_t)z * Tn * Tn;
#pragma unroll
    for (int i = 0; i < 4; i++)
#pragma unroll
        for (int j = 0; j < 4; j++)
            out[(size_t)(row0 + ty * 4 + i) * Tn + col0 + tx * 4 + j] =
                acc[i][j] * 0.125f;
}

// ---------------- softmax (causal) * w ----------------
__global__ void softmax_w_kernel(const float* __restrict__ time_w,
                                 const float* __restrict__ alpha,
                                 const float* __restrict__ beta) {
    __shared__ float sh[256];
    int t = blockIdx.x;
    int z = blockIdx.y;
    int h = z % Hn;
    float* arow = g_att + ((size_t)z * Tn + t) * Tn;
    int len = t + 1;
    float mx = -1e30f;
    for (int u = threadIdx.x; u < len; u += 256) mx = fmaxf(mx, arow[u]);
    mx = blockReduceMax(mx, sh);
    float sum = 0.f;
    for (int u = threadIdx.x; u < len; u += 256) sum += expf(arow[u] - mx);
    sum = blockReduceSum(sum, sh);
    float inv = 1.f / sum;
    float bt = beta[h * Tn + t];
    for (int u = threadIdx.x; u < Tn; u += 256) {
        if (u < len) {
            float w = time_w[h * TTn + (TTn - 1 - t + u)] * alpha[h * Tn + u] * bt;
            arow[u] = expf(arow[u] - mx) * inv * w;
        } else {
            arow[u] = 0.f;
        }
    }
}

// ---------------- head mixing ----------------
__global__ void mix_kernel(const float* __restrict__ Wmix) {
    __shared__ float wm[256];
    if (threadIdx.x < 256) wm[threadIdx.x] = Wmix[threadIdx.x];
    __syncthreads();
    int idx = blockIdx.x * 256 + threadIdx.x;
    if (idx >= Bn * Tn * Tn) return;
    int b = idx / (Tn * Tn);
    int rr = idx % (Tn * Tn);
    int t = rr / Tn, u = rr % Tn;
    size_t base = (size_t)b * Hn * Tn * Tn + rr;
    const size_t stride = (size_t)Tn * Tn;
    if (u > t) {
#pragma unroll
        for (int i = 0; i < Hn; i++) g_att2[base + i * stride] = 0.f;
        return;
    }
    float vals[Hn];
#pragma unroll
    for (int j = 0; j < Hn; j++) vals[j] = g_att[base + j * stride];
#pragma unroll
    for (int i = 0; i < Hn; i++) {
        float s = 0.f;
#pragma unroll
        for (int j = 0; j < Hn; j++) s += wm[i * Hn + j] * vals[j];
        g_att2[base + i * stride] = s;
    }
}

// ---------------- y = att2 @ v ----------------
__global__ __launch_bounds__(256)
void av_kernel() {
    int z = blockIdx.z;
    int row0 = blockIdx.y * 64;
    const float* Am = g_att2 + (size_t)z * Tn * Tn;
    const float* Vm = g_v    + (size_t)z * Tn * HSn;
    __shared__ float As[16][68];
    __shared__ float Bs[16][64];
    int tid = threadIdx.x;
    int tx = tid % 16, ty = tid / 16;
    int ar = tid / 4, akq = (tid % 4) * 4;
    int bkk = tid / 16, bc = (tid % 16) * 4;
    float acc[4][4] = {};
    int klim = row0 + 64;
    for (int k0 = 0; k0 < klim; k0 += 16) {
        float4 av = *(const float4*)(Am + (size_t)(row0 + ar) * Tn + k0 + akq);
        As[akq + 0][ar] = av.x; As[akq + 1][ar] = av.y;
        As[akq + 2][ar] = av.z; As[akq + 3][ar] = av.w;
        float4 bv = *(const float4*)(Vm + (size_t)(k0 + bkk) * HSn + bc);
        *(float4*)&Bs[bkk][bc] = bv;
        __syncthreads();
#pragma unroll
        for (int kk = 0; kk < 16; kk++) {
            float4 ra = *(const float4*)&As[kk][ty * 4];
            float4 rb = *(const float4*)&Bs[kk][tx * 4];
            float a4[4] = {ra.x, ra.y, ra.z, ra.w};
            float b4[4] = {rb.x, rb.y, rb.z, rb.w};
#pragma unroll
            for (int i = 0; i < 4; i++)
#pragma unroll
                for (int j = 0; j < 4; j++)
                    acc[i][j] += a4[i] * b4[j];
        }
        __syncthreads();
    }
    int b = z / Hn, h = z % Hn;
#pragma unroll
    for (int i = 0; i < 4; i++) {
        int t = row0 + ty * 4 + i;
#pragma unroll
        for (int j = 0; j < 4; j++) {
            int d = tx * 4 + j;
            g_y[((size_t)b * Tn + t) * Cn + h * HSn + d] = acc[i][j];
        }
    }
}

// ---------------- launch ----------------
extern "C" void kernel_launch(void* const* d_in, const int* in_sizes, int n_in,
                              void* d_out, int out_size) {
    const float* x         = (const float*)d_in[0];
    const float* ln1_g     = (const float*)d_in[1];
    const float* ln1_b     = (const float*)d_in[2];
    const float* Wq        = (const float*)d_in[3];
    const float* bq        = (const float*)d_in[4];
    const float* Wk        = (const float*)d_in[5];
    const float* bk        = (const float*)d_in[6];
    const float* Wv        = (const float*)d_in[7];
    const float* bv        = (const float*)d_in[8];
    const float* Wo        = (const float*)d_in[9];
    const float* bo        = (const float*)d_in[10];
    const float* time_w    = (const float*)d_in[11];
    const float* time_alpha= (const float*)d_in[12];
    const float* time_beta = (const float*)d_in[13];
    const float* time_gamma= (const float*)d_in[14];
    const float* Wmix      = (const float*)d_in[15];
    const float* ln2_g     = (const float*)d_in[16];
    const float* ln2_b     = (const float*)d_in[17];
    const float* Wgk       = (const float*)d_in[18];
    const float* bgk       = (const float*)d_in[19];
    const float* Wgv       = (const float*)d_in[20];
    const float* bgv       = (const float*)d_in[21];
    const float* Wgw       = (const float*)d_in[22];
    const float* bgw       = (const float*)d_in[23];

    float *xs, *q, *k, *v, *x1, *xm, *kkb, *gvb, *yb;
    cudaGetSymbolAddress((void**)&xs,  g_xs);
    cudaGetSymbolAddress((void**)&q,   g_q);
    cudaGetSymbolAddress((void**)&k,   g_k);
    cudaGetSymbolAddress((void**)&v,   g_v);
    cudaGetSymbolAddress((void**)&yb,  g_y);
    cudaGetSymbolAddress((void**)&x1,  g_x1);
    cudaGetSymbolAddress((void**)&xm,  g_xm);
    cudaGetSymbolAddress((void**)&kkb, g_kk);
    cudaGetSymbolAddress((void**)&gvb, g_gv);

    const int M = Bn * Tn;   // 2048
    dim3 gCC(Cn / 128, M / 128);       // 8 x 16
    dim3 gCF(FFNn / 128, M / 128);     // 32 x 16

    // 1) LN1 + time shift
    ln1_shift_kernel<<<Bn * Tn, 256>>>(x, ln1_g, ln1_b);

    // 2) QKV projections
    gemm_mma<<<gCC, 256>>>(xs, Wq, bq, q, M, Cn, Cn, EPI_QKV, nullptr, nullptr);
    gemm_mma<<<gCC, 256>>>(xs, Wk, bk, k, M, Cn, Cn, EPI_QKV, nullptr, nullptr);
    gemm_mma<<<gCC, 256>>>(xs, Wv, bv, v, M, Cn, Cn, EPI_QKV, nullptr, nullptr);

    // 3) rotary
    rotary_kernel<<<(Bn * Hn * Tn * 16) / 256, 256>>>();

    // 4) scores
    scores_kernel<<<dim3(Tn / 64, Tn / 64, Bn * Hn), 256>>>();

    // 5) softmax * w
    softmax_w_kernel<<<dim3(Tn, Bn * Hn), 256>>>(time_w, time_alpha, time_beta);

    // 6) head mix
    mix_kernel<<<(Bn * Tn * Tn) / 256, 256>>>(Wmix);

    // 7) y = att2 @ v
    av_kernel<<<dim3(1, Tn / 64, Bn * Hn), 256>>>();

    // 8) out projection
    gemm_mma<<<gCC, 256>>>(yb, Wo, bo, x1, M, Cn, Cn, EPI_OUT, time_gamma, x);

    // 9) LN2
    ln_kernel<<<Bn * Tn, 256>>>(x1, ln2_g, ln2_b, xm);

    // 10-12) FFN
    gemm_mma<<<gCF, 256>>>(xm, Wgk, bgk, kkb, M, FFNn, Cn, EPI_GELU, nullptr, nullptr);
    gemm_mma<<<gCF, 256>>>(xm, Wgv, bgv, gvb, M, FFNn, Cn, EPI_MUL, kkb, nullptr);
    gemm_mma<<<gCC, 256>>>(gvb, Wgw, bgw, (float*)d_out, M, Cn, FFNn, EPI_ADD, x1, nullptr);
}

// round 4
// speedup vs baseline: 4.9019x; 1.3556x over previous
#include <cuda_runtime.h>
#include <cstdint>
#include <math.h>

#define Bn   2
#define Tn   1024
#define Cn   1024
#define Hn   16
#define HSn  64
#define TTn  1024
#define FFNn 4096
#define EPSn 1e-6f

// ---------------- scratch (device globals; no allocations allowed) ----------
__device__ float g_xs [Bn*Tn*Cn];
__device__ float g_q  [Bn*Tn*Cn];
__device__ float g_k  [Bn*Tn*Cn];
__device__ float g_v  [Bn*Tn*Cn];
__device__ float g_att [Bn*Hn*Tn*Tn];
__device__ float g_att2[Bn*Hn*Tn*Tn];
__device__ float g_y  [Bn*Tn*Cn];
__device__ float g_x1 [Bn*Tn*Cn];
__device__ float g_xm [Bn*Tn*Cn];
__device__ float g_kk [Bn*Tn*FFNn];
__device__ float g_gv [Bn*Tn*FFNn];

// ---------------- helpers ----------------
__device__ __forceinline__ float rnd_tf32(float v) {
    uint32_t t;
    asm("cvt.rna.tf32.f32 %0, %1;" : "=r"(t) : "f"(v));
    return __uint_as_float(t);
}
__device__ __forceinline__ void mma_tf32(float* d, const uint32_t* a, const uint32_t* b) {
    asm volatile(
        "mma.sync.aligned.m16n8k8.row.col.f32.tf32.tf32.f32 "
        "{%0,%1,%2,%3}, {%4,%5,%6,%7}, {%8,%9}, {%0,%1,%2,%3};"
        : "+f"(d[0]), "+f"(d[1]), "+f"(d[2]), "+f"(d[3])
        : "r"(a[0]), "r"(a[1]), "r"(a[2]), "r"(a[3]), "r"(b[0]), "r"(b[1]));
}
__device__ __forceinline__ uint32_t smem_u32(const void* p) {
    uint32_t a;
    asm("{ .reg .u64 t; cvta.to.shared.u64 t, %1; cvt.u32.u64 %0, t; }"
        : "=r"(a) : "l"(p));
    return a;
}
__device__ __forceinline__ void cp16(uint32_t dst, const void* src) {
    asm volatile("cp.async.ca.shared.global [%0], [%1], 16;" :: "r"(dst), "l"(src));
}
__device__ __forceinline__ void cp_commit() {
    asm volatile("cp.async.commit_group;" ::: "memory");
}
template<int N> __device__ __forceinline__ void cp_wait() {
    asm volatile("cp.async.wait_group %0;" :: "n"(N) : "memory");
}

// ---------------- block reductions ----------------
__device__ __forceinline__ float blockReduceSum(float v, float* sh) {
    int tid = threadIdx.x;
    sh[tid] = v; __syncthreads();
    for (int s = 128; s > 0; s >>= 1) {
        if (tid < s) sh[tid] += sh[tid + s];
        __syncthreads();
    }
    float r = sh[0]; __syncthreads();
    return r;
}
__device__ __forceinline__ float blockReduceMax(float v, float* sh) {
    int tid = threadIdx.x;
    sh[tid] = v; __syncthreads();
    for (int s = 128; s > 0; s >>= 1) {
        if (tid < s) sh[tid] = fmaxf(sh[tid], sh[tid + s]);
        __syncthreads();
    }
    float r = sh[0]; __syncthreads();
    return r;
}

// ---------------- LN1 + time_shift_half (tf32-rounded output) ---------------
__global__ void ln1_shift_kernel(const float* __restrict__ x,
                                 const float* __restrict__ g,
                                 const float* __restrict__ b) {
    __shared__ float sh[256];
    int bt = blockIdx.x;
    int bb = bt / Tn, t = bt % Tn;
    const float* row = x + (size_t)bt * Cn;
    float s = 0.f, s2 = 0.f;
    for (int c = threadIdx.x; c < Cn; c += 256) {
        float v = row[c]; s += v; s2 += v * v;
    }
    s  = blockReduceSum(s,  sh);
    s2 = blockReduceSum(s2, sh);
    float m    = s / Cn;
    float rstd = rsqrtf(s2 / Cn - m * m + EPSn);
    for (int c = threadIdx.x; c < Cn; c += 256) {
        float yv = rnd_tf32((row[c] - m) * rstd * g[c] + b[c]);
        if (c < Cn / 2) {
            if (t + 1 < Tn) g_xs[((size_t)bb * Tn + t + 1) * Cn + c] = yv;
        } else {
            g_xs[(size_t)bt * Cn + c] = yv;
        }
    }
    if (t == 0) {
        for (int c = threadIdx.x; c < Cn / 2; c += 256)
            g_xs[(size_t)bb * Tn * Cn + c] = 0.f;
    }
}

// ---------------- plain LayerNorm (tf32-rounded output) ----------------
__global__ void ln_kernel(const float* __restrict__ in,
                          const float* __restrict__ g,
                          const float* __restrict__ b,
                          float* __restrict__ out) {
    __shared__ float sh[256];
    int bt = blockIdx.x;
    const float* row = in + (size_t)bt * Cn;
    float s = 0.f, s2 = 0.f;
    for (int c = threadIdx.x; c < Cn; c += 256) {
        float v = row[c]; s += v; s2 += v * v;
    }
    s  = blockReduceSum(s,  sh);
    s2 = blockReduceSum(s2, sh);
    float m    = s / Cn;
    float rstd = rsqrtf(s2 / Cn - m * m + EPSn);
    for (int c = threadIdx.x; c < Cn; c += 256)
        out[(size_t)bt * Cn + c] = rnd_tf32((row[c] - m) * rstd * g[c] + b[c]);
}

// ---------------- tf32 mma GEMM w/ cp.async: C[M,N]=A[M,K]@B[K,N] -----------
// A pre-rounded to tf32 by producer; B raw fp32 (HW truncates to tf32).
#define EPI_QKV   1
#define EPI_OUT   2
#define EPI_GELU  3
#define EPI_MUL   4
#define EPI_ADD   5

#define ASTR 36    // smem A row stride (floats)
#define BSTR 136   // smem B row stride (floats)
#define ABUF (128*ASTR)
#define BBUF (32*BSTR)
#define GEMM_SMEM ((2*ABUF + 2*BBUF)*4)

__global__ __launch_bounds__(256, 2)
void gemm_mma(const float* __restrict__ A, const float* __restrict__ Bm,
              const float* __restrict__ bias, float* __restrict__ C,
              int M, int N, int K, int mode,
              const float* __restrict__ aux1, const float* __restrict__ aux2) {
    extern __shared__ float dsm[];
    uint32_t* usm = (uint32_t*)dsm;
    uint32_t sAu = smem_u32(dsm);
    uint32_t sBu = sAu + 2 * ABUF * 4;

    int tid = threadIdx.x;
    int lane = tid & 31;
    int wid  = tid >> 5;
    int wm = wid >> 2;            // 0..1
    int wn = wid & 3;             // 0..3
    int row0 = blockIdx.y * 128, col0 = blockIdx.x * 128;
    int lg = lane >> 2;           // 0..7
    int lq = lane & 3;            // 0..3

    float acc[4][4][4] = {};

    // copy thread mapping
    int arow = tid >> 3, acol = (tid & 7) * 4;     // A: 32 rows/iter
    int brow = tid >> 5, bcol = (tid & 31) * 4;    // B: 8 rows/iter

    const int nch = K >> 5;

    const float* Abase = A + (size_t)(row0 + arow) * K + acol;
    const float* Bbase = Bm + (size_t)brow * N + col0 + bcol;
    uint32_t adst0 = sAu + (arow * ASTR + acol) * 4;
    uint32_t bdst0 = sBu + (brow * BSTR + bcol) * 4;

#define ISSUE(ci) do { \
    int _p = (ci) & 1; int _k0 = (ci) << 5; \
    const float* _as = Abase + _k0; \
    uint32_t _ad = adst0 + _p * ABUF * 4; \
    _Pragma("unroll") \
    for (int _it = 0; _it < 4; _it++) \
        cp16(_ad + _it * 32 * ASTR * 4, _as + (size_t)_it * 32 * K); \
    const float* _bs = Bbase + (size_t)_k0 * N; \
    uint32_t _bd = bdst0 + _p * BBUF * 4; \
    _Pragma("unroll") \
    for (int _it = 0; _it < 4; _it++) \
        cp16(_bd + _it * 8 * BSTR * 4, _bs + (size_t)_it * 8 * N); \
} while (0)

    ISSUE(0); cp_commit();

    for (int ci = 0; ci < nch; ci++) {
        cp_wait<0>();
        __syncthreads();
        if (ci + 1 < nch) { ISSUE(ci + 1); cp_commit(); }

        const uint32_t* uA = usm + (ci & 1) * ABUF;
        const uint32_t* uB = usm + 2 * ABUF + (ci & 1) * BBUF;
#pragma unroll
        for (int ks = 0; ks < 4; ks++) {
            int kb = ks * 8;
            uint32_t af[4][4], bf[4][2];
#pragma unroll
            for (int mi = 0; mi < 4; mi++) {
                int mr = wm * 64 + mi * 16 + lg;
                af[mi][0] = uA[mr * ASTR + kb + lq];
                af[mi][1] = uA[(mr + 8) * ASTR + kb + lq];
                af[mi][2] = uA[mr * ASTR + kb + 4 + lq];
                af[mi][3] = uA[(mr + 8) * ASTR + kb + 4 + lq];
            }
#pragma unroll
            for (int ni = 0; ni < 4; ni++) {
                int nc = wn * 32 + ni * 8 + lg;
                bf[ni][0] = uB[(kb + lq) * BSTR + nc];
                bf[ni][1] = uB[(kb + 4 + lq) * BSTR + nc];
            }
#pragma unroll
            for (int mi = 0; mi < 4; mi++)
#pragma unroll
                for (int ni = 0; ni < 4; ni++)
                    mma_tf32(acc[mi][ni], af[mi], bf[ni]);
        }
        __syncthreads();
    }
#undef ISSUE

    // epilogue
#pragma unroll
    for (int mi = 0; mi < 4; mi++) {
#pragma unroll
        for (int ni = 0; ni < 4; ni++) {
#pragma unroll
            for (int half = 0; half < 2; half++) {
                int r = row0 + wm * 64 + mi * 16 + lg + half * 8;
                int c = col0 + wn * 32 + ni * 8 + lq * 2;
                float v0 = acc[mi][ni][half * 2 + 0] + bias[c];
                float v1 = acc[mi][ni][half * 2 + 1] + bias[c + 1];
                size_t oi = (size_t)r * N + c;
                switch (mode) {
                case EPI_QKV: {
                    int bI = r / Tn, t = r % Tn, h = c / HSn, d = c % HSn;
                    size_t qi = (((size_t)bI * Hn + h) * Tn + t) * HSn + d;
                    C[qi]     = rnd_tf32(v0);
                    C[qi + 1] = rnd_tf32(v1);
                } break;
                case EPI_OUT: {
                    int t = r % Tn;
                    C[oi]     = v0 * aux1[t] + aux2[oi];
                    C[oi + 1] = v1 * aux1[t] + aux2[oi + 1];
                } break;
                case EPI_GELU:
                    C[oi]     = 0.5f * v0 * (1.f + erff(v0 * 0.70710678118654752f));
                    C[oi + 1] = 0.5f * v1 * (1.f + erff(v1 * 0.70710678118654752f));
                    break;
                case EPI_MUL:
                    C[oi]     = rnd_tf32(v0 * aux1[oi]);
                    C[oi + 1] = rnd_tf32(v1 * aux1[oi + 1]);
                    break;
                case EPI_ADD:
                    C[oi]     = v0 + aux1[oi];
                    C[oi + 1] = v1 + aux1[oi + 1];
                    break;
                default:
                    C[oi] = v0; C[oi + 1] = v1;
                }
            }
        }
    }
}

// ---------------- rotary on q,k (tf32-rounded output) ----------------
__global__ void rotary_kernel() {
    int idx = blockIdx.x * blockDim.x + threadIdx.x;
    if (idx >= Bn * Hn * Tn * 16) return;
    int i = idx & 15;
    int bht = idx >> 4;
    int t = bht % Tn;
    float inv = powf((float)TTn, -(float)i / 16.0f);
    float ang = (float)t * inv;
    float cv = cosf(ang), sv = sinf(ang);
    float* qp = g_q + (size_t)bht * HSn;
    float* kp = g_k + (size_t)bht * HSn;
    float a = qp[i], b2 = qp[i + 16];
    qp[i]      = rnd_tf32(a * cv - b2 * sv);
    qp[i + 16] = rnd_tf32(b2 * cv + a * sv);
    a = kp[i]; b2 = kp[i + 16];
    kp[i]      = rnd_tf32(a * cv - b2 * sv);
    kp[i + 16] = rnd_tf32(b2 * cv + a * sv);
}

// ---------------- scores via mma: att[t][u] = q[t]·k[u] * 0.125 -------------
#define SSTR 68
#define SCORES_SMEM (2*128*SSTR*4)
__global__ __launch_bounds__(256, 2)
void scores_mma() {
    int ut = blockIdx.x, tt = blockIdx.y;
    if (ut > tt) return;                      // strictly above diagonal
    int z = blockIdx.z;
    int row0 = tt * 128, col0 = ut * 128;
    const float* q = g_q + (size_t)z * Tn * HSn;
    const float* k = g_k + (size_t)z * Tn * HSn;

    extern __shared__ float dsm[];
    uint32_t* sq = (uint32_t*)dsm;            // [128][SSTR]
    uint32_t* sk = sq + 128 * SSTR;           // [128][SSTR]

    int tid = threadIdx.x;
    int lane = tid & 31, wid = tid >> 5;
    int wm = wid >> 2, wn = wid & 3;
    int lg = lane >> 2, lq = lane & 3;

    // load q,k tiles: 128 rows x 64 cols each
    {
        int r = tid >> 4, c = (tid & 15) * 4;
#pragma unroll
        for (int it = 0; it < 8; it++) {
            int rr = it * 16 + r;
            *(float4*)((float*)sq + rr * SSTR + c) =
                *(const float4*)(q + (size_t)(row0 + rr) * HSn + c);
            *(float4*)((float*)sk + rr * SSTR + c) =
                *(const float4*)(k + (size_t)(col0 + rr) * HSn + c);
        }
    }
    __syncthreads();

    float acc[4][4][4] = {};
#pragma unroll
    for (int ks = 0; ks < 8; ks++) {
        int kb = ks * 8;
        uint32_t af[4][4], bf[4][2];
#pragma unroll
        for (int mi = 0; mi < 4; mi++) {
            int mr = wm * 64 + mi * 16 + lg;
            af[mi][0] = sq[mr * SSTR + kb + lq];
            af[mi][1] = sq[(mr + 8) * SSTR + kb + lq];
            af[mi][2] = sq[mr * SSTR + kb + 4 + lq];
            af[mi][3] = sq[(mr + 8) * SSTR + kb + 4 + lq];
        }
#pragma unroll
        for (int ni = 0; ni < 4; ni++) {
            int nc = wn * 32 + ni * 8 + lg;     // u index
            bf[ni][0] = sk[nc * SSTR + kb + lq];
            bf[ni][1] = sk[nc * SSTR + kb + 4 + lq];
        }
#pragma unroll
        for (int mi = 0; mi < 4; mi++)
#pragma unroll
            for (int ni = 0; ni < 4; ni++)
                mma_tf32(acc[mi][ni], af[mi], bf[ni]);
    }

    float* out = g_att + (size_t)z * Tn * Tn;
#pragma unroll
    for (int mi = 0; mi < 4; mi++)
#pragma unroll
        for (int ni = 0; ni < 4; ni++)
#pragma unroll
            for (int half = 0; half < 2; half++) {
                int r = row0 + wm * 64 + mi * 16 + lg + half * 8;
                int c = col0 + wn * 32 + ni * 8 + lq * 2;
                out[(size_t)r * Tn + c]     = acc[mi][ni][half * 2 + 0] * 0.125f;
                out[(size_t)r * Tn + c + 1] = acc[mi][ni][half * 2 + 1] * 0.125f;
            }
}

// ---------------- softmax (causal) * w ----------------
__global__ void softmax_w_kernel(const float* __restrict__ time_w,
                                 const float* __restrict__ alpha,
                                 const float* __restrict__ beta) {
    __shared__ float sh[256];
    int t = blockIdx.x;
    int z = blockIdx.y;
    int h = z % Hn;
    float* arow = g_att + ((size_t)z * Tn + t) * Tn;
    int len = t + 1;
    float mx = -1e30f;
    for (int u = threadIdx.x; u < len; u += 256) mx = fmaxf(mx, arow[u]);
    mx = blockReduceMax(mx, sh);
    float sum = 0.f;
    for (int u = threadIdx.x; u < len; u += 256) sum += expf(arow[u] - mx);
    sum = blockReduceSum(sum, sh);
    float inv = 1.f / sum;
    float bt = beta[h * Tn + t];
    for (int u = threadIdx.x; u < Tn; u += 256) {
        if (u < len) {
            float w = time_w[h * TTn + (TTn - 1 - t + u)] * alpha[h * Tn + u] * bt;
            arow[u] = expf(arow[u] - mx) * inv * w;
        } else {
            arow[u] = 0.f;
        }
    }
}

// ---------------- head mixing (tf32-rounded output) ----------------
__global__ void mix_kernel(const float* __restrict__ Wmix) {
    __shared__ float wm[256];
    if (threadIdx.x < 256) wm[threadIdx.x] = Wmix[threadIdx.x];
    __syncthreads();
    int idx = blockIdx.x * 256 + threadIdx.x;
    if (idx >= Bn * Tn * Tn) return;
    int b = idx / (Tn * Tn);
    int rr = idx % (Tn * Tn);
    int t = rr / Tn, u = rr % Tn;
    size_t base = (size_t)b * Hn * Tn * Tn + rr;
    const size_t stride = (size_t)Tn * Tn;
    if (u > t) {
#pragma unroll
        for (int i = 0; i < Hn; i++) g_att2[base + i * stride] = 0.f;
        return;
    }
    float vals[Hn];
#pragma unroll
    for (int j = 0; j < Hn; j++) vals[j] = g_att[base + j * stride];
#pragma unroll
    for (int i = 0; i < Hn; i++) {
        float s = 0.f;
#pragma unroll
        for (int j = 0; j < Hn; j++) s += wm[i * Hn + j] * vals[j];
        g_att2[base + i * stride] = rnd_tf32(s);
    }
}

// ---------------- y = att2 @ v via mma (K clipped causally) -----------------
#define AVASTR 36
#define AVVSTR 72
__global__ __launch_bounds__(256, 2)
void av_mma() {
    __shared__ uint32_t sa2[128 * AVASTR];
    __shared__ uint32_t sv [32 * AVVSTR];
    int tt = blockIdx.x;           // t-tile (8)
    int z  = blockIdx.y;           // b*H + h (32)
    int row0 = tt * 128;
    const float* Am = g_att2 + (size_t)z * Tn * Tn;
    const float* Vm = g_v    + (size_t)z * Tn * HSn;

    int tid = threadIdx.x;
    int lane = tid & 31, wid = tid >> 5;
    int wm2 = wid >> 1;            // 0..3 (32 rows each)
    int wn2 = wid & 1;             // 0..1 (32 cols each)
    int lg = lane >> 2, lq = lane & 3;

    float acc[2][4][4] = {};

    int ar = tid >> 3, ac = (tid & 7) * 4;   // A: 32 rows/iter, 4 iters
    int vr = tid >> 3, vc = (tid & 7) * 4;   // V: 32 rows, 2 col-iters

    int klim = row0 + 128;
    for (int k0 = 0; k0 < klim; k0 += 32) {
#pragma unroll
        for (int it = 0; it < 4; it++) {
            int r = it * 32 + ar;
            float4 v4 = *(const float4*)(Am + (size_t)(row0 + r) * Tn + k0 + ac);
            uint32_t* p = &sa2[r * AVASTR + ac];
            p[0] = __float_as_uint(v4.x); p[1] = __float_as_uint(v4.y);
            p[2] = __float_as_uint(v4.z); p[3] = __float_as_uint(v4.w);
        }
#pragma unroll
        for (int it = 0; it < 2; it++) {
            float4 v4 = *(const float4*)(Vm + (size_t)(k0 + vr) * HSn + it * 32 + vc);
            uint32_t* p = &sv[vr * AVVSTR + it * 32 + vc];
            p[0] = __float_as_uint(v4.x); p[1] = __float_as_uint(v4.y);
            p[2] = __float_as_uint(v4.z); p[3] = __float_as_uint(v4.w);
        }
        __syncthreads();
#pragma unroll
        for (int ks = 0; ks < 4; ks++) {
            int kb = ks * 8;
            uint32_t af[2][4], bf[4][2];
#pragma unroll
            for (int mi = 0; mi < 2; mi++) {
                int mr = wm2 * 32 + mi * 16 + lg;
                af[mi][0] = sa2[mr * AVASTR + kb + lq];
                af[mi][1] = sa2[(mr + 8) * AVASTR + kb + lq];
                af[mi][2] = sa2[mr * AVASTR + kb + 4 + lq];
                af[mi][3] = sa2[(mr + 8) * AVASTR + kb + 4 + lq];
            }
#pragma unroll
            for (int ni = 0; ni < 4; ni++) {
                int nc = wn2 * 32 + ni * 8 + lg;
                bf[ni][0] = sv[(kb + lq) * AVVSTR + nc];
                bf[ni][1] = sv[(kb + 4 + lq) * AVVSTR + nc];
            }
#pragma unroll
            for (int mi = 0; mi < 2; mi++)
#pragma unroll
                for (int ni = 0; ni < 4; ni++)
                    mma_tf32(acc[mi][ni], af[mi], bf[ni]);
        }
        __syncthreads();
    }

    int b = z / Hn, h = z % Hn;
#pragma unroll
    for (int mi = 0; mi < 2; mi++)
#pragma unroll
        for (int ni = 0; ni < 4; ni++)
#pragma unroll
            for (int half = 0; half < 2; half++) {
                int t = row0 + wm2 * 32 + mi * 16 + lg + half * 8;
                int d = wn2 * 32 + ni * 8 + lq * 2;
                size_t oi = ((size_t)b * Tn + t) * Cn + h * HSn + d;
                g_y[oi]     = rnd_tf32(acc[mi][ni][half * 2 + 0]);
                g_y[oi + 1] = rnd_tf32(acc[mi][ni][half * 2 + 1]);
            }
}

// ---------------- launch ----------------
extern "C" void kernel_launch(void* const* d_in, const int* in_sizes, int n_in,
                              void* d_out, int out_size) {
    const float* x         = (const float*)d_in[0];
    const float* ln1_g     = (const float*)d_in[1];
    const float* ln1_b     = (const float*)d_in[2];
    const float* Wq        = (const float*)d_in[3];
    const float* bq        = (const float*)d_in[4];
    const float* Wk        = (const float*)d_in[5];
    const float* bk        = (const float*)d_in[6];
    const float* Wv        = (const float*)d_in[7];
    const float* bv        = (const float*)d_in[8];
    const float* Wo        = (const float*)d_in[9];
    const float* bo        = (const float*)d_in[10];
    const float* time_w    = (const float*)d_in[11];
    const float* time_alpha= (const float*)d_in[12];
    const float* time_beta = (const float*)d_in[13];
    const float* time_gamma= (const float*)d_in[14];
    const float* Wmix      = (const float*)d_in[15];
    const float* ln2_g     = (const float*)d_in[16];
    const float* ln2_b     = (const float*)d_in[17];
    const float* Wgk       = (const float*)d_in[18];
    const float* bgk       = (const float*)d_in[19];
    const float* Wgv       = (const float*)d_in[20];
    const float* bgv       = (const float*)d_in[21];
    const float* Wgw       = (const float*)d_in[22];
    const float* bgw       = (const float*)d_in[23];

    float *xs, *q, *k, *v, *x1, *xm, *kkb, *gvb, *yb;
    cudaGetSymbolAddress((void**)&xs,  g_xs);
    cudaGetSymbolAddress((void**)&q,   g_q);
    cudaGetSymbolAddress((void**)&k,   g_k);
    cudaGetSymbolAddress((void**)&v,   g_v);
    cudaGetSymbolAddress((void**)&yb,  g_y);
    cudaGetSymbolAddress((void**)&x1,  g_x1);
    cudaGetSymbolAddress((void**)&xm,  g_xm);
    cudaGetSymbolAddress((void**)&kkb, g_kk);
    cudaGetSymbolAddress((void**)&gvb, g_gv);

    static bool attr_done = false;
    if (!attr_done) {
        cudaFuncSetAttribute(gemm_mma, cudaFuncAttributeMaxDynamicSharedMemorySize, GEMM_SMEM);
        cudaFuncSetAttribute(scores_mma, cudaFuncAttributeMaxDynamicSharedMemorySize, SCORES_SMEM);
        attr_done = true;
    }

    const int M = Bn * Tn;   // 2048
    dim3 gCC(Cn / 128, M / 128);       // 8 x 16
    dim3 gCF(FFNn / 128, M / 128);     // 32 x 16

    // 1) LN1 + time shift
    ln1_shift_kernel<<<Bn * Tn, 256>>>(x, ln1_g, ln1_b);

    // 2) QKV projections
    gemm_mma<<<gCC, 256, GEMM_SMEM>>>(xs, Wq, bq, q, M, Cn, Cn, EPI_QKV, nullptr, nullptr);
    gemm_mma<<<gCC, 256, GEMM_SMEM>>>(xs, Wk, bk, k, M, Cn, Cn, EPI_QKV, nullptr, nullptr);
    gemm_mma<<<gCC, 256, GEMM_SMEM>>>(xs, Wv, bv, v, M, Cn, Cn, EPI_QKV, nullptr, nullptr);

    // 3) rotary
    rotary_kernel<<<(Bn * Hn * Tn * 16) / 256, 256>>>();

    // 4) scores (mma, causal tiles)
    scores_mma<<<dim3(Tn / 128, Tn / 128, Bn * Hn), 256, SCORES_SMEM>>>();

    // 5) softmax * w
    softmax_w_kernel<<<dim3(Tn, Bn * Hn), 256>>>(time_w, time_alpha, time_beta);

    // 6) head mix
    mix_kernel<<<(Bn * Tn * Tn) / 256, 256>>>(Wmix);

    // 7) y = att2 @ v (mma)
    av_mma<<<dim3(Tn / 128, Bn * Hn), 256>>>();

    // 8) out projection
    gemm_mma<<<gCC, 256, GEMM_SMEM>>>(yb, Wo, bo, x1, M, Cn, Cn, EPI_OUT, time_gamma, x);

    // 9) LN2
    ln_kernel<<<Bn * Tn, 256>>>(x1, ln2_g, ln2_b, xm);

    // 10-12) FFN
    gemm_mma<<<gCF, 256, GEMM_SMEM>>>(xm, Wgk, bgk, kkb, M, FFNn, Cn, EPI_GELU, nullptr, nullptr);
    gemm_mma<<<gCF, 256, GEMM_SMEM>>>(xm, Wgv, bgv, gvb, M, FFNn, Cn, EPI_MUL, kkb, nullptr);
    gemm_mma<<<gCC, 256, GEMM_SMEM>>>(gvb, Wgw, bgw, (float*)d_out, M, Cn, FFNn, EPI_ADD, x1, nullptr);
}

// round 5
// speedup vs baseline: 5.4595x; 1.1137x over previous
#include <cuda_runtime.h>
#include <cstdint>
#include <math.h>

#define Bn   2
#define Tn   1024
#define Cn   1024
#define Hn   16
#define HSn  64
#define TTn  1024
#define FFNn 4096
#define EPSn 1e-6f

// ---------------- scratch ----------------
__device__ float g_xs [Bn*Tn*Cn];
__device__ float g_q  [Bn*Tn*Cn];
__device__ float g_k  [Bn*Tn*Cn];
__device__ float g_v  [Bn*Tn*Cn];
__device__ float g_att [Bn*Hn*Tn*Tn];
__device__ float g_att2[Bn*Hn*Tn*Tn];
__device__ float g_y  [Bn*Tn*Cn];
__device__ float g_x1 [Bn*Tn*Cn];
__device__ float g_xm [Bn*Tn*Cn];
__device__ float g_kk [Bn*Tn*FFNn];
__device__ float g_gv [Bn*Tn*FFNn];

// ---------------- helpers ----------------
__device__ __forceinline__ float rnd_tf32(float v) {
    uint32_t t;
    asm("cvt.rna.tf32.f32 %0, %1;" : "=r"(t) : "f"(v));
    return __uint_as_float(t);
}
__device__ __forceinline__ void mma_tf32(float* d, const uint32_t* a, const uint32_t* b) {
    asm volatile(
        "mma.sync.aligned.m16n8k8.row.col.f32.tf32.tf32.f32 "
        "{%0,%1,%2,%3}, {%4,%5,%6,%7}, {%8,%9}, {%0,%1,%2,%3};"
        : "+f"(d[0]), "+f"(d[1]), "+f"(d[2]), "+f"(d[3])
        : "r"(a[0]), "r"(a[1]), "r"(a[2]), "r"(a[3]), "r"(b[0]), "r"(b[1]));
}
__device__ __forceinline__ uint32_t smem_u32(const void* p) {
    uint32_t a;
    asm("{ .reg .u64 t; cvta.to.shared.u64 t, %1; cvt.u32.u64 %0, t; }"
        : "=r"(a) : "l"(p));
    return a;
}
__device__ __forceinline__ void cp16(uint32_t dst, const void* src) {
    asm volatile("cp.async.ca.shared.global [%0], [%1], 16;" :: "r"(dst), "l"(src));
}
__device__ __forceinline__ void cp_commit() {
    asm volatile("cp.async.commit_group;" ::: "memory");
}
template<int N> __device__ __forceinline__ void cp_wait() {
    asm volatile("cp.async.wait_group %0;" :: "n"(N) : "memory");
}

// ---------------- block reductions ----------------
__device__ __forceinline__ float blockReduceSum(float v, float* sh) {
    int tid = threadIdx.x;
    sh[tid] = v; __syncthreads();
    for (int s = 128; s > 0; s >>= 1) {
        if (tid < s) sh[tid] += sh[tid + s];
        __syncthreads();
    }
    float r = sh[0]; __syncthreads();
    return r;
}

// ---------------- LN1 + time_shift_half ----------------
__global__ void ln1_shift_kernel(const float* __restrict__ x,
                                 const float* __restrict__ g,
                                 const float* __restrict__ b) {
    __shared__ float sh[256];
    int bt = blockIdx.x;
    int bb = bt / Tn, t = bt % Tn;
    const float* row = x + (size_t)bt * Cn;
    float s = 0.f, s2 = 0.f;
    for (int c = threadIdx.x; c < Cn; c += 256) {
        float v = row[c]; s += v; s2 += v * v;
    }
    s  = blockReduceSum(s,  sh);
    s2 = blockReduceSum(s2, sh);
    float m    = s / Cn;
    float rstd = rsqrtf(s2 / Cn - m * m + EPSn);
    for (int c = threadIdx.x; c < Cn; c += 256) {
        float yv = rnd_tf32((row[c] - m) * rstd * g[c] + b[c]);
        if (c < Cn / 2) {
            if (t + 1 < Tn) g_xs[((size_t)bb * Tn + t + 1) * Cn + c] = yv;
        } else {
            g_xs[(size_t)bt * Cn + c] = yv;
        }
    }
    if (t == 0) {
        for (int c = threadIdx.x; c < Cn / 2; c += 256)
            g_xs[(size_t)bb * Tn * Cn + c] = 0.f;
    }
}

// ---------------- plain LayerNorm ----------------
__global__ void ln_kernel(const float* __restrict__ in,
                          const float* __restrict__ g,
                          const float* __restrict__ b,
                          float* __restrict__ out) {
    __shared__ float sh[256];
    int bt = blockIdx.x;
    const float* row = in + (size_t)bt * Cn;
    float s = 0.f, s2 = 0.f;
    for (int c = threadIdx.x; c < Cn; c += 256) {
        float v = row[c]; s += v; s2 += v * v;
    }
    s  = blockReduceSum(s,  sh);
    s2 = blockReduceSum(s2, sh);
    float m    = s / Cn;
    float rstd = rsqrtf(s2 / Cn - m * m + EPSn);
    for (int c = threadIdx.x; c < Cn; c += 256)
        out[(size_t)bt * Cn + c] = rnd_tf32((row[c] - m) * rstd * g[c] + b[c]);
}

// ================= GEMM 128x128 tile =================
#define EPI_QKV   1
#define EPI_OUT   2
#define EPI_GELU  3
#define EPI_MUL   4
#define EPI_ADD   5

#define ASTR 36
#define BSTR 136
#define ABUF (128*ASTR)
#define BBUF (32*BSTR)
#define GEMM_SMEM ((2*ABUF + 2*BBUF)*4)

template<int MODE>
__device__ __forceinline__ void gemm_body128(
    float* dsm, const float* __restrict__ A, const float* __restrict__ Bm,
    const float* __restrict__ bias, float* __restrict__ C,
    int N, int K,
    const float* __restrict__ aux1, const float* __restrict__ aux2,
    int row0, int col0) {
    uint32_t* usm = (uint32_t*)dsm;
    uint32_t sAu = smem_u32(dsm);
    uint32_t sBu = sAu + 2 * ABUF * 4;

    int tid = threadIdx.x;
    int lane = tid & 31;
    int wid  = tid >> 5;
    int wm = wid >> 2, wn = wid & 3;
    int lg = lane >> 2, lq = lane & 3;

    float acc[4][4][4] = {};

    int arow = tid >> 3, acol = (tid & 7) * 4;
    int brow = tid >> 5, bcol = (tid & 31) * 4;

    const int nch = K >> 5;
    const float* Abase = A + (size_t)(row0 + arow) * K + acol;
    const float* Bbase = Bm + (size_t)brow * N + col0 + bcol;
    uint32_t adst0 = sAu + (arow * ASTR + acol) * 4;
    uint32_t bdst0 = sBu + (brow * BSTR + bcol) * 4;

#define ISSUE128(ci) do { \
    int _p = (ci) & 1; int _k0 = (ci) << 5; \
    const float* _as = Abase + _k0; \
    uint32_t _ad = adst0 + _p * ABUF * 4; \
    _Pragma("unroll") \
    for (int _it = 0; _it < 4; _it++) \
        cp16(_ad + _it * 32 * ASTR * 4, _as + (size_t)_it * 32 * K); \
    const float* _bs = Bbase + (size_t)_k0 * N; \
    uint32_t _bd = bdst0 + _p * BBUF * 4; \
    _Pragma("unroll") \
    for (int _it = 0; _it < 4; _it++) \
        cp16(_bd + _it * 8 * BSTR * 4, _bs + (size_t)_it * 8 * N); \
} while (0)

    ISSUE128(0); cp_commit();

    for (int ci = 0; ci < nch; ci++) {
        cp_wait<0>();
        __syncthreads();
        if (ci + 1 < nch) { ISSUE128(ci + 1); cp_commit(); }

        const uint32_t* uA = usm + (ci & 1) * ABUF;
        const uint32_t* uB = usm + 2 * ABUF + (ci & 1) * BBUF;
#pragma unroll
        for (int ks = 0; ks < 4; ks++) {
            int kb = ks * 8;
            uint32_t af[4][4], bf[4][2];
#pragma unroll
            for (int mi = 0; mi < 4; mi++) {
                int mr = wm * 64 + mi * 16 + lg;
                af[mi][0] = uA[mr * ASTR + kb + lq];
                af[mi][1] = uA[(mr + 8) * ASTR + kb + lq];
                af[mi][2] = uA[mr * ASTR + kb + 4 + lq];
                af[mi][3] = uA[(mr + 8) * ASTR + kb + 4 + lq];
            }
#pragma unroll
            for (int ni = 0; ni < 4; ni++) {
                int nc = wn * 32 + ni * 8 + lg;
                bf[ni][0] = uB[(kb + lq) * BSTR + nc];
                bf[ni][1] = uB[(kb + 4 + lq) * BSTR + nc];
            }
#pragma unroll
            for (int mi = 0; mi < 4; mi++)
#pragma unroll
                for (int ni = 0; ni < 4; ni++)
                    mma_tf32(acc[mi][ni], af[mi], bf[ni]);
        }
        __syncthreads();
    }
#undef ISSUE128

#pragma unroll
    for (int mi = 0; mi < 4; mi++) {
#pragma unroll
        for (int ni = 0; ni < 4; ni++) {
#pragma unroll
            for (int half = 0; half < 2; half++) {
                int r = row0 + wm * 64 + mi * 16 + lg + half * 8;
                int c = col0 + wn * 32 + ni * 8 + lq * 2;
                float v0 = acc[mi][ni][half * 2 + 0] + bias[c];
                float v1 = acc[mi][ni][half * 2 + 1] + bias[c + 1];
                size_t oi = (size_t)r * N + c;
                if (MODE == EPI_QKV) {
                    int bI = r / Tn, t = r % Tn, h = c / HSn, d = c % HSn;
                    size_t qi = (((size_t)bI * Hn + h) * Tn + t) * HSn + d;
                    C[qi]     = rnd_tf32(v0);
                    C[qi + 1] = rnd_tf32(v1);
                } else if (MODE == EPI_OUT) {
                    int t = r % Tn;
                    C[oi]     = v0 * aux1[t] + aux2[oi];
                    C[oi + 1] = v1 * aux1[t] + aux2[oi + 1];
                } else if (MODE == EPI_ADD) {
                    C[oi]     = v0 + aux1[oi];
                    C[oi + 1] = v1 + aux1[oi + 1];
                } else {
                    C[oi] = v0; C[oi + 1] = v1;
                }
            }
        }
    }
}

struct TriPtr {
    const float *W0, *W1, *W2;
    const float *b0, *b1, *b2;
    float *o0, *o1, *o2;
};

__global__ __launch_bounds__(256, 2)
void gemm_qkv(const float* __restrict__ A, TriPtr p, int N, int K) {
    extern __shared__ float dsm[];
    int z = blockIdx.z;
    const float* W = (z == 0) ? p.W0 : (z == 1) ? p.W1 : p.W2;
    const float* bb = (z == 0) ? p.b0 : (z == 1) ? p.b1 : p.b2;
    float* o = (z == 0) ? p.o0 : (z == 1) ? p.o1 : p.o2;
    gemm_body128<EPI_QKV>(dsm, A, W, bb, o, N, K, nullptr, nullptr,
                          blockIdx.y * 128, blockIdx.x * 128);
}

template<int MODE>
__global__ __launch_bounds__(256, 2)
void gemm128(const float* __restrict__ A, const float* __restrict__ Bm,
             const float* __restrict__ bias, float* __restrict__ C,
             int N, int K,
             const float* __restrict__ aux1, const float* __restrict__ aux2) {
    extern __shared__ float dsm[];
    gemm_body128<MODE>(dsm, A, Bm, bias, C, N, K, aux1, aux2,
                       blockIdx.y * 128, blockIdx.x * 128);
}

// ================= GEMM 128x256 tile (FFN) =================
#define A2STR 36
#define B2STR 264
#define A2BUF (128*A2STR)
#define B2BUF (32*B2STR)
#define GEMM_SMEM256 ((2*A2BUF + 2*B2BUF)*4)

template<int MODE>
__global__ __launch_bounds__(256)
void gemm256(const float* __restrict__ A, const float* __restrict__ Bm,
             const float* __restrict__ bias, float* __restrict__ C,
             int N, int K, const float* __restrict__ aux1) {
    extern __shared__ float dsm[];
    uint32_t* usm = (uint32_t*)dsm;
    uint32_t sAu = smem_u32(dsm);
    uint32_t sBu = sAu + 2 * A2BUF * 4;

    int tid = threadIdx.x;
    int lane = tid & 31;
    int wid  = tid >> 5;
    int wm = wid >> 2, wn = wid & 3;     // 2 x 4 warps, warp tile 64x64
    int lg = lane >> 2, lq = lane & 3;
    int row0 = blockIdx.y * 128, col0 = blockIdx.x * 256;

    float acc[4][8][4] = {};

    int arow = tid >> 3, acol = (tid & 7) * 4;
    int brow = tid >> 6, bcol = (tid & 63) * 4;

    const int nch = K >> 5;
    const float* Abase = A + (size_t)(row0 + arow) * K + acol;
    const float* Bbase = Bm + (size_t)brow * N + col0 + bcol;
    uint32_t adst0 = sAu + (arow * A2STR + acol) * 4;
    uint32_t bdst0 = sBu + (brow * B2STR + bcol) * 4;

#define ISSUE256(ci) do { \
    int _p = (ci) & 1; int _k0 = (ci) << 5; \
    const float* _as = Abase + _k0; \
    uint32_t _ad = adst0 + _p * A2BUF * 4; \
    _Pragma("unroll") \
    for (int _it = 0; _it < 4; _it++) \
        cp16(_ad + _it * 32 * A2STR * 4, _as + (size_t)_it * 32 * K); \
    const float* _bs = Bbase + (size_t)_k0 * N; \
    uint32_t _bd = bdst0 + _p * B2BUF * 4; \
    _Pragma("unroll") \
    for (int _it = 0; _it < 8; _it++) \
        cp16(_bd + _it * 4 * B2STR * 4, _bs + (size_t)_it * 4 * N); \
} while (0)

    ISSUE256(0); cp_commit();

    for (int ci = 0; ci < nch; ci++) {
        cp_wait<0>();
        __syncthreads();
        if (ci + 1 < nch) { ISSUE256(ci + 1); cp_commit(); }

        const uint32_t* uA = usm + (ci & 1) * A2BUF;
        const uint32_t* uB = usm + 2 * A2BUF + (ci & 1) * B2BUF;
#pragma unroll
        for (int ks = 0; ks < 4; ks++) {
            int kb = ks * 8;
            uint32_t af[4][4], bf[8][2];
#pragma unroll
            for (int mi = 0; mi < 4; mi++) {
                int mr = wm * 64 + mi * 16 + lg;
                af[mi][0] = uA[mr * A2STR + kb + lq];
                af[mi][1] = uA[(mr + 8) * A2STR + kb + lq];
                af[mi][2] = uA[mr * A2STR + kb + 4 + lq];
                af[mi][3] = uA[(mr + 8) * A2STR + kb + 4 + lq];
            }
#pragma unroll
            for (int ni = 0; ni < 8; ni++) {
                int nc = wn * 64 + ni * 8 + lg;
                bf[ni][0] = uB[(kb + lq) * B2STR + nc];
                bf[ni][1] = uB[(kb + 4 + lq) * B2STR + nc];
            }
#pragma unroll
            for (int mi = 0; mi < 4; mi++)
#pragma unroll
                for (int ni = 0; ni < 8; ni++)
                    mma_tf32(acc[mi][ni], af[mi], bf[ni]);
        }
        __syncthreads();
    }
#undef ISSUE256

#pragma unroll
    for (int mi = 0; mi < 4; mi++) {
#pragma unroll
        for (int ni = 0; ni < 8; ni++) {
#pragma unroll
            for (int half = 0; half < 2; half++) {
                int r = row0 + wm * 64 + mi * 16 + lg + half * 8;
                int c = col0 + wn * 64 + ni * 8 + lq * 2;
                float v0 = acc[mi][ni][half * 2 + 0] + bias[c];
                float v1 = acc[mi][ni][half * 2 + 1] + bias[c + 1];
                size_t oi = (size_t)r * N + c;
                if (MODE == EPI_GELU) {
                    C[oi]     = 0.5f * v0 * (1.f + erff(v0 * 0.70710678118654752f));
                    C[oi + 1] = 0.5f * v1 * (1.f + erff(v1 * 0.70710678118654752f));
                } else {  // EPI_MUL
                    C[oi]     = rnd_tf32(v0 * aux1[oi]);
                    C[oi + 1] = rnd_tf32(v1 * aux1[oi + 1]);
                }
            }
        }
    }
}

// ---------------- rotary on q,k ----------------
__global__ void rotary_kernel() {
    int idx = blockIdx.x * blockDim.x + threadIdx.x;
    if (idx >= Bn * Hn * Tn * 16) return;
    int i = idx & 15;
    int bht = idx >> 4;
    int t = bht % Tn;
    float inv = powf((float)TTn, -(float)i / 16.0f);
    float ang = (float)t * inv;
    float cv = cosf(ang), sv = sinf(ang);
    float* qp = g_q + (size_t)bht * HSn;
    float* kp = g_k + (size_t)bht * HSn;
    float a = qp[i], b2 = qp[i + 16];
    qp[i]      = rnd_tf32(a * cv - b2 * sv);
    qp[i + 16] = rnd_tf32(b2 * cv + a * sv);
    a = kp[i]; b2 = kp[i + 16];
    kp[i]      = rnd_tf32(a * cv - b2 * sv);
    kp[i + 16] = rnd_tf32(b2 * cv + a * sv);
}

// ---------------- scores via mma ----------------
#define SSTR 68
#define SCORES_SMEM (2*128*SSTR*4)
__global__ __launch_bounds__(256, 2)
void scores_mma() {
    int ut = blockIdx.x, tt = blockIdx.y;
    if (ut > tt) return;
    int z = blockIdx.z;
    int row0 = tt * 128, col0 = ut * 128;
    const float* q = g_q + (size_t)z * Tn * HSn;
    const float* k = g_k + (size_t)z * Tn * HSn;

    extern __shared__ float dsm[];
    uint32_t* sq = (uint32_t*)dsm;
    uint32_t* sk = sq + 128 * SSTR;

    int tid = threadIdx.x;
    int lane = tid & 31, wid = tid >> 5;
    int wm = wid >> 2, wn = wid & 3;
    int lg = lane >> 2, lq = lane & 3;

    {
        int r = tid >> 4, c = (tid & 15) * 4;
#pragma unroll
        for (int it = 0; it < 8; it++) {
            int rr = it * 16 + r;
            *(float4*)((float*)sq + rr * SSTR + c) =
                *(const float4*)(q + (size_t)(row0 + rr) * HSn + c);
            *(float4*)((float*)sk + rr * SSTR + c) =
                *(const float4*)(k + (size_t)(col0 + rr) * HSn + c);
        }
    }
    __syncthreads();

    float acc[4][4][4] = {};
#pragma unroll
    for (int ks = 0; ks < 8; ks++) {
        int kb = ks * 8;
        uint32_t af[4][4], bf[4][2];
#pragma unroll
        for (int mi = 0; mi < 4; mi++) {
            int mr = wm * 64 + mi * 16 + lg;
            af[mi][0] = sq[mr * SSTR + kb + lq];
            af[mi][1] = sq[(mr + 8) * SSTR + kb + lq];
            af[mi][2] = sq[mr * SSTR + kb + 4 + lq];
            af[mi][3] = sq[(mr + 8) * SSTR + kb + 4 + lq];
        }
#pragma unroll
        for (int ni = 0; ni < 4; ni++) {
            int nc = wn * 32 + ni * 8 + lg;
            bf[ni][0] = sk[nc * SSTR + kb + lq];
            bf[ni][1] = sk[nc * SSTR + kb + 4 + lq];
        }
#pragma unroll
        for (int mi = 0; mi < 4; mi++)
#pragma unroll
            for (int ni = 0; ni < 4; ni++)
                mma_tf32(acc[mi][ni], af[mi], bf[ni]);
    }

    float* out = g_att + (size_t)z * Tn * Tn;
#pragma unroll
    for (int mi = 0; mi < 4; mi++)
#pragma unroll
        for (int ni = 0; ni < 4; ni++)
#pragma unroll
            for (int half = 0; half < 2; half++) {
                int r = row0 + wm * 64 + mi * 16 + lg + half * 8;
                int c = col0 + wn * 32 + ni * 8 + lq * 2;
                out[(size_t)r * Tn + c]     = acc[mi][ni][half * 2 + 0] * 0.125f;
                out[(size_t)r * Tn + c + 1] = acc[mi][ni][half * 2 + 1] * 0.125f;
            }
}

// ---------------- fused softmax (causal) * w + head-mix ----------------
#define SMIX_SMEM ((Hn*Tn + 256) * 4)
__global__ __launch_bounds__(256)
void softmax_mix(const float* __restrict__ time_w,
                 const float* __restrict__ alpha,
                 const float* __restrict__ beta,
                 const float* __restrict__ Wmix) {
    extern __shared__ float sm[];
    float* p  = sm;                 // [16][1024]
    float* wm = sm + Hn * Tn;       // [256]
    int t = blockIdx.x, b = blockIdx.y;
    int tid = threadIdx.x, lane = tid & 31, w = tid >> 5;
    if (tid < 256) wm[tid] = Wmix[tid];
    int len = t + 1;

#pragma unroll
    for (int hh = 0; hh < 2; hh++) {
        int h = w * 2 + hh;
        const float* src = g_att + (((size_t)b * Hn + h) * Tn + t) * Tn;
        float* ph = p + h * Tn;
        float mx = -1e30f;
        for (int u = lane; u < len; u += 32) {
            float v = src[u]; ph[u] = v; mx = fmaxf(mx, v);
        }
#pragma unroll
        for (int o = 16; o; o >>= 1) mx = fmaxf(mx, __shfl_xor_sync(0xFFFFFFFFu, mx, o));
        float sum = 0.f;
        for (int u = lane; u < len; u += 32) {
            float e = expf(ph[u] - mx); ph[u] = e; sum += e;
        }
#pragma unroll
        for (int o = 16; o; o >>= 1) sum += __shfl_xor_sync(0xFFFFFFFFu, sum, o);
        float inv = 1.f / sum;
        float bt = beta[h * Tn + t];
        const float* twr = time_w + h * TTn + (TTn - 1 - t);
        const float* alr = alpha + h * Tn;
        for (int u = lane; u < len; u += 32)
            ph[u] *= inv * twr[u] * alr[u] * bt;
    }
    __syncthreads();

    int zend = (t / 128) * 128 + 128;   // zero upper region within av's k-tile
    const size_t stride = (size_t)Tn * Tn;
    for (int u = tid; u < zend; u += 256) {
        size_t obase = (((size_t)b * Hn) * Tn + t) * Tn + u;
        if (u < len) {
            float vals[Hn];
#pragma unroll
            for (int j = 0; j < Hn; j++) vals[j] = p[j * Tn + u];
#pragma unroll
            for (int i = 0; i < Hn; i++) {
                float s = 0.f;
#pragma unroll
                for (int j = 0; j < Hn; j++) s += wm[i * Hn + j] * vals[j];
                g_att2[obase + i * stride] = rnd_tf32(s);
            }
        } else {
#pragma unroll
            for (int i = 0; i < Hn; i++) g_att2[obase + i * stride] = 0.f;
        }
    }
}

// ---------------- y = att2 @ v via mma (K clipped causally) -----------------
#define AVASTR 36
#define AVVSTR 72
__global__ __launch_bounds__(256, 2)
void av_mma() {
    __shared__ uint32_t sa2[128 * AVASTR];
    __shared__ uint32_t sv [32 * AVVSTR];
    int tt = blockIdx.x;
    int z  = blockIdx.y;
    int row0 = tt * 128;
    const float* Am = g_att2 + (size_t)z * Tn * Tn;
    const float* Vm = g_v    + (size_t)z * Tn * HSn;

    int tid = threadIdx.x;
    int lane = tid & 31, wid = tid >> 5;
    int wm2 = wid >> 1;
    int wn2 = wid & 1;
    int lg = lane >> 2, lq = lane & 3;

    float acc[2][4][4] = {};

    int ar = tid >> 3, ac = (tid & 7) * 4;
    int vr = tid >> 3, vc = (tid & 7) * 4;

    int klim = row0 + 128;
    for (int k0 = 0; k0 < klim; k0 += 32) {
#pragma unroll
        for (int it = 0; it < 4; it++) {
            int r = it * 32 + ar;
            float4 v4 = *(const float4*)(Am + (size_t)(row0 + r) * Tn + k0 + ac);
            uint32_t* p = &sa2[r * AVASTR + ac];
            p[0] = __float_as_uint(v4.x); p[1] = __float_as_uint(v4.y);
            p[2] = __float_as_uint(v4.z); p[3] = __float_as_uint(v4.w);
        }
#pragma unroll
        for (int it = 0; it < 2; it++) {
            float4 v4 = *(const float4*)(Vm + (size_t)(k0 + vr) * HSn + it * 32 + vc);
            uint32_t* p = &sv[vr * AVVSTR + it * 32 + vc];
            p[0] = __float_as_uint(v4.x); p[1] = __float_as_uint(v4.y);
            p[2] = __float_as_uint(v4.z); p[3] = __float_as_uint(v4.w);
        }
        __syncthreads();
#pragma unroll
        for (int ks = 0; ks < 4; ks++) {
            int kb = ks * 8;
            uint32_t af[2][4], bf[4][2];
#pragma unroll
            for (int mi = 0; mi < 2; mi++) {
                int mr = wm2 * 32 + mi * 16 + lg;
                af[mi][0] = sa2[mr * AVASTR + kb + lq];
                af[mi][1] = sa2[(mr + 8) * AVASTR + kb + lq];
                af[mi][2] = sa2[mr * AVASTR + kb + 4 + lq];
                af[mi][3] = sa2[(mr + 8) * AVASTR + kb + 4 + lq];
            }
#pragma unroll
            for (int ni = 0; ni < 4; ni++) {
                int nc = wn2 * 32 + ni * 8 + lg;
                bf[ni][0] = sv[(kb + lq) * AVVSTR + nc];
                bf[ni][1] = sv[(kb + 4 + lq) * AVVSTR + nc];
            }
#pragma unroll
            for (int mi = 0; mi < 2; mi++)
#pragma unroll
                for (int ni = 0; ni < 4; ni++)
                    mma_tf32(acc[mi][ni], af[mi], bf[ni]);
        }
        __syncthreads();
    }

    int b = z / Hn, h = z % Hn;
#pragma unroll
    for (int mi = 0; mi < 2; mi++)
#pragma unroll
        for (int ni = 0; ni < 4; ni++)
#pragma unroll
            for (int half = 0; half < 2; half++) {
                int t = row0 + wm2 * 32 + mi * 16 + lg + half * 8;
                int d = wn2 * 32 + ni * 8 + lq * 2;
                size_t oi = ((size_t)b * Tn + t) * Cn + h * HSn + d;
                g_y[oi]     = rnd_tf32(acc[mi][ni][half * 2 + 0]);
                g_y[oi + 1] = rnd_tf32(acc[mi][ni][half * 2 + 1]);
            }
}

// ---------------- launch ----------------
extern "C" void kernel_launch(void* const* d_in, const int* in_sizes, int n_in,
                              void* d_out, int out_size) {
    const float* x         = (const float*)d_in[0];
    const float* ln1_g     = (const float*)d_in[1];
    const float* ln1_b     = (const float*)d_in[2];
    const float* Wq        = (const float*)d_in[3];
    const float* bq        = (const float*)d_in[4];
    const float* Wk        = (const float*)d_in[5];
    const float* bk        = (const float*)d_in[6];
    const float* Wv        = (const float*)d_in[7];
    const float* bv        = (const float*)d_in[8];
    const float* Wo        = (const float*)d_in[9];
    const float* bo        = (const float*)d_in[10];
    const float* time_w    = (const float*)d_in[11];
    const float* time_alpha= (const float*)d_in[12];
    const float* time_beta = (const float*)d_in[13];
    const float* time_gamma= (const float*)d_in[14];
    const float* Wmix      = (const float*)d_in[15];
    const float* ln2_g     = (const float*)d_in[16];
    const float* ln2_b     = (const float*)d_in[17];
    const float* Wgk       = (const float*)d_in[18];
    const float* bgk       = (const float*)d_in[19];
    const float* Wgv       = (const float*)d_in[20];
    const float* bgv       = (const float*)d_in[21];
    const float* Wgw       = (const float*)d_in[22];
    const float* bgw       = (const float*)d_in[23];

    float *xs, *q, *k, *v, *x1, *xm, *kkb, *gvb, *yb;
    cudaGetSymbolAddress((void**)&xs,  g_xs);
    cudaGetSymbolAddress((void**)&q,   g_q);
    cudaGetSymbolAddress((void**)&k,   g_k);
    cudaGetSymbolAddress((void**)&v,   g_v);
    cudaGetSymbolAddress((void**)&yb,  g_y);
    cudaGetSymbolAddress((void**)&x1,  g_x1);
    cudaGetSymbolAddress((void**)&xm,  g_xm);
    cudaGetSymbolAddress((void**)&kkb, g_kk);
    cudaGetSymbolAddress((void**)&gvb, g_gv);

    static bool attr_done = false;
    if (!attr_done) {
        cudaFuncSetAttribute(gemm_qkv, cudaFuncAttributeMaxDynamicSharedMemorySize, GEMM_SMEM);
        cudaFuncSetAttribute(gemm128<EPI_OUT>, cudaFuncAttributeMaxDynamicSharedMemorySize, GEMM_SMEM);
        cudaFuncSetAttribute(gemm128<EPI_ADD>, cudaFuncAttributeMaxDynamicSharedMemorySize, GEMM_SMEM);
        cudaFuncSetAttribute(gemm256<EPI_GELU>, cudaFuncAttributeMaxDynamicSharedMemorySize, GEMM_SMEM256);
        cudaFuncSetAttribute(gemm256<EPI_MUL>, cudaFuncAttributeMaxDynamicSharedMemorySize, GEMM_SMEM256);
        cudaFuncSetAttribute(scores_mma, cudaFuncAttributeMaxDynamicSharedMemorySize, SCORES_SMEM);
        cudaFuncSetAttribute(softmax_mix, cudaFuncAttributeMaxDynamicSharedMemorySize, SMIX_SMEM);
        attr_done = true;
    }

    const int M = Bn * Tn;   // 2048

    // 1) LN1 + time shift
    ln1_shift_kernel<<<Bn * Tn, 256>>>(x, ln1_g, ln1_b);

    // 2) QKV fused (384 blocks)
    TriPtr tp = {Wq, Wk, Wv, bq, bk, bv, q, k, v};
    gemm_qkv<<<dim3(Cn / 128, M / 128, 3), 256, GEMM_SMEM>>>(xs, tp, Cn, Cn);

    // 3) rotary
    rotary_kernel<<<(Bn * Hn * Tn * 16) / 256, 256>>>();

    // 4) scores
    scores_mma<<<dim3(Tn / 128, Tn / 128, Bn * Hn), 256, SCORES_SMEM>>>();

    // 5+6) softmax * w + head mix (fused)
    softmax_mix<<<dim3(Tn, Bn), 256, SMIX_SMEM>>>(time_w, time_alpha, time_beta, Wmix);

    // 7) y = att2 @ v
    av_mma<<<dim3(Tn / 128, Bn * Hn), 256>>>();

    // 8) out projection
    gemm128<EPI_OUT><<<dim3(Cn / 128, M / 128), 256, GEMM_SMEM>>>(
        yb, Wo, bo, x1, Cn, Cn, time_gamma, x);

    // 9) LN2
    ln_kernel<<<Bn * Tn, 256>>>(x1, ln2_g, ln2_b, xm);

    // 10-12) FFN
    gemm256<EPI_GELU><<<dim3(FFNn / 256, M / 128), 256, GEMM_SMEM256>>>(
        xm, Wgk, bgk, kkb, FFNn, Cn, nullptr);
    gemm256<EPI_MUL><<<dim3(FFNn / 256, M / 128), 256, GEMM_SMEM256>>>(
        xm, Wgv, bgv, gvb, FFNn, Cn, kkb);
    gemm128<EPI_ADD><<<dim3(Cn / 128, M / 128), 256, GEMM_SMEM>>>(
        gvb, Wgw, bgw, (float*)d_out, Cn, FFNn, x1, nullptr);
}